// round 2
// baseline (speedup 1.0000x reference)
#include <cuda_runtime.h>
#include <cuda_fp16.h>
#include <cstdint>

// ============================================================================
// Problem constants
// ============================================================================
#define B_DIM  2
#define N_DIM  1024
#define M_DIM  256
#define D_DIM  576
#define H1_DIM 512
#define H2_DIM 256

// Scratch (allocation-free rule: __device__ globals)
__device__ float  g_aproj[B_DIM * N_DIM * H1_DIM];   // a_proj
__device__ float  g_bproj[B_DIM * M_DIM * H1_DIM];   // b_proj + b1
__device__ __half g_w2h[H2_DIM * H1_DIM];            // W2^T as fp16: [j][k]

// ============================================================================
// PTX helpers (base ISA only — target is compute_103 WITHOUT the 'a' suffix,
// so no tcgen05/TMEM. mma.sync + cp.async are fine.)
// ============================================================================
__device__ __forceinline__ uint32_t smem_to_u32(const void* p) {
    uint32_t a;
    asm("{ .reg .u64 t; cvta.to.shared.u64 t, %1; cvt.u32.u64 %0, t; }" : "=r"(a) : "l"(p));
    return a;
}

__device__ __forceinline__ void cp16(uint32_t s, const void* g) {
    asm volatile("cp.async.cg.shared.global [%0], [%1], 16;" :: "r"(s), "l"(g) : "memory");
}
__device__ __forceinline__ void cp_commit() {
    asm volatile("cp.async.commit_group;" ::: "memory");
}

__device__ __forceinline__ void ldm_x4(uint32_t addr, uint32_t& r0, uint32_t& r1,
                                       uint32_t& r2, uint32_t& r3) {
    asm volatile("ldmatrix.sync.aligned.m8n8.x4.shared.b16 {%0,%1,%2,%3}, [%4];"
                 : "=r"(r0), "=r"(r1), "=r"(r2), "=r"(r3) : "r"(addr));
}

__device__ __forceinline__ void mma_f16(float* c, const uint32_t* a, uint32_t b0, uint32_t b1) {
    asm volatile(
        "mma.sync.aligned.m16n8k16.row.col.f32.f16.f16.f32 "
        "{%0,%1,%2,%3}, {%4,%5,%6,%7}, {%8,%9}, {%0,%1,%2,%3};"
        : "+f"(c[0]), "+f"(c[1]), "+f"(c[2]), "+f"(c[3])
        : "r"(a[0]), "r"(a[1]), "r"(a[2]), "r"(a[3]), "r"(b0), "r"(b1));
}

// ============================================================================
// Prep kernel 1: projection GEMM  out[r, h] = X[r, :576] @ W[:576, h] (+ bias)
// ============================================================================
__global__ __launch_bounds__(256) void proj_kernel(
    const float* __restrict__ X, const float* __restrict__ W,
    const float* __restrict__ bias, float* __restrict__ out)
{
    __shared__ float As[16][65];
    __shared__ float Bs[16][65];
    const int tid = threadIdx.x;
    const int r0 = blockIdx.x * 64;
    const int c0 = blockIdx.y * 64;
    const int tx = tid & 15;
    const int ty = tid >> 4;
    float acc[4][4] = {};

    for (int k0 = 0; k0 < D_DIM; k0 += 16) {
        #pragma unroll
        for (int i = tid; i < 64 * 16; i += 256) {
            int m = i >> 4, k = i & 15;
            As[k][m] = X[(size_t)(r0 + m) * D_DIM + k0 + k];
        }
        #pragma unroll
        for (int i = tid; i < 16 * 64; i += 256) {
            int k = i >> 6, c = i & 63;
            Bs[k][c] = W[(size_t)(k0 + k) * H1_DIM + c0 + c];
        }
        __syncthreads();
        #pragma unroll
        for (int kk = 0; kk < 16; kk++) {
            float a[4], b[4];
            #pragma unroll
            for (int i = 0; i < 4; i++) a[i] = As[kk][ty * 4 + i];
            #pragma unroll
            for (int j = 0; j < 4; j++) b[j] = Bs[kk][tx * 4 + j];
            #pragma unroll
            for (int i = 0; i < 4; i++)
                #pragma unroll
                for (int j = 0; j < 4; j++) acc[i][j] += a[i] * b[j];
        }
        __syncthreads();
    }
    #pragma unroll
    for (int i = 0; i < 4; i++)
        #pragma unroll
        for (int j = 0; j < 4; j++) {
            int r = r0 + ty * 4 + i, c = c0 + tx * 4 + j;
            out[(size_t)r * H1_DIM + c] = acc[i][j] + (bias ? bias[c] : 0.0f);
        }
}

// ============================================================================
// Prep kernel 2: W2 (512x256) -> W2^T fp16 (256x512)
// ============================================================================
__global__ void w2_half_kernel(const float* __restrict__ W2, __half* __restrict__ W2H) {
    __shared__ float t[32][33];
    const int k0 = blockIdx.x * 32;
    const int j0 = blockIdx.y * 32;
    const int x = threadIdx.x, y = threadIdx.y;  // 32 x 8
    #pragma unroll
    for (int dy = 0; dy < 32; dy += 8)
        t[y + dy][x] = W2[(size_t)(k0 + y + dy) * H2_DIM + j0 + x];
    __syncthreads();
    #pragma unroll
    for (int dy = 0; dy < 32; dy += 8)
        W2H[(size_t)(j0 + y + dy) * H1_DIM + k0 + x] = __float2half_rn(t[x][y + dy]);
}

// ============================================================================
// Main fused kernel
//   CTA: 1 n x 128 m-pairs x all 256 h2; K=512 in 8 stages of 64.
//   bproj fp32 cp.async-staged -> fused relu(a+b) -> fp16 A tile in SMEM.
//   W2^T fp16 cp.async-staged. mma.sync m16n8k16, fp32 accum in registers.
//   Epilogue: relu(+b2) dot w3 fused, shfl + smem reduce, single store.
// ============================================================================
static constexpr int KC      = 64;
static constexpr int NSTAGE  = H1_DIM / KC;          // 8
static constexpr int A_STRH  = 72;                   // halves per row (pad)
static constexpr int B_STRH  = 72;
static constexpr int BS_STRF = 68;                   // floats per row (pad)
static constexpr int A_BYTES  = 128 * A_STRH * 2;    // 18432
static constexpr int BB_BYTES = 256 * B_STRH * 2;    // 36864
static constexpr int BS_BYTES = 128 * BS_STRF * 4;   // 34816

static constexpr int SM_AROW = 0;                    // 512 f32
static constexpr int SM_B2   = 2048;                 // 256 f32
static constexpr int SM_W3   = 3072;                 // 256 f32
static constexpr int SM_PART = 4096;                 // 128*4 f32
static constexpr int SM_BSTG = 6144;                 // 2 x BS_BYTES
static constexpr int SM_A    = SM_BSTG + 2 * BS_BYTES;   // 75776
static constexpr int SM_B    = SM_A + 2 * A_BYTES;       // 112640
static constexpr int SMEM_MAIN_TOTAL = SM_B + 2 * BB_BYTES;  // 186368

__global__ __launch_bounds__(512, 1) void pair_mlp_main(
    const float* __restrict__ aproj, const float* __restrict__ bproj,
    const __half* __restrict__ w2h, const float* __restrict__ b2,
    const float* __restrict__ w3, const float* __restrict__ b3,
    float* __restrict__ out)
{
    extern __shared__ __align__(128) char smem[];
    const uint32_t smem_base = smem_to_u32(smem);
    const int tid = threadIdx.x;
    const int wid = tid >> 5;
    const int lid = tid & 31;
    const int wr  = wid >> 2;   // warp row band (0..3): rows wr*32
    const int wc  = wid & 3;    // warp col band (0..3): cols wc*64
    const int g   = lid >> 2;   // mma group id
    const int tg  = lid & 3;    // thread-in-group

    const int t  = blockIdx.x;            // 0..4095
    const int b  = t >> 11;
    const int n  = (t >> 1) & (N_DIM - 1);
    const int m0 = (t & 1) * 128;

    float* s_arow = (float*)(smem + SM_AROW);
    float* s_b2   = (float*)(smem + SM_B2);
    float* s_w3   = (float*)(smem + SM_W3);
    float* s_part = (float*)(smem + SM_PART);

    const float* arow_g = aproj + (size_t)(b * N_DIM + n) * H1_DIM;
    if (tid < H1_DIM) s_arow[tid] = arow_g[tid];
    if (tid < H2_DIM) { s_b2[tid] = b2[tid]; s_w3[tid] = w3[tid]; }

    const float* bprow = bproj + (size_t)(b * M_DIM + m0) * H1_DIM;

    // ---- cp.async stage issue ----
    auto issue_stage = [&](int s) {
        const int buf = s & 1;
        const int kc = s * KC;
        // bproj fp32: 128 rows x 64 floats = 2048 x 16B
        {
            uint32_t sbase = smem_base + SM_BSTG + buf * BS_BYTES;
            #pragma unroll
            for (int i = 0; i < 4; i++) {
                int idx = tid + i * 512;
                int row = idx >> 4, ch = idx & 15;
                cp16(sbase + row * (BS_STRF * 4) + ch * 16,
                     bprow + (size_t)row * H1_DIM + kc + ch * 4);
            }
        }
        // W2^T fp16: 256 rows x 64 halves = 2048 x 16B
        {
            uint32_t sbase = smem_base + SM_B + buf * BB_BYTES;
            #pragma unroll
            for (int i = 0; i < 4; i++) {
                int idx = tid + i * 512;
                int row = idx >> 3, ch = idx & 7;
                cp16(sbase + row * (B_STRH * 2) + ch * 16,
                     w2h + (size_t)row * H1_DIM + kc + ch * 8);
            }
        }
        cp_commit();
    };

    issue_stage(0);

    float acc[2][8][4];
    #pragma unroll
    for (int mt = 0; mt < 2; mt++)
        #pragma unroll
        for (int nt = 0; nt < 8; nt++)
            #pragma unroll
            for (int q = 0; q < 4; q++) acc[mt][nt][q] = 0.0f;

    // ldmatrix lane address components
    const int sel = lid >> 3, lr = lid & 7;
    const uint32_t a_row_base = wr * 32 + (sel & 1) * 8 + lr;   // + mt*16
    const uint32_t a_colb     = (sel >> 1) * 16;                // + kk*32
    const uint32_t b_row_base = wc * 64 + (sel >> 1) * 8 + lr;  // + ntp*16
    const uint32_t b_colb     = (sel & 1) * 16;                 // + kk*32

    const int fr_row = tid >> 2;       // A-fill row 0..127
    const int fr_seg = tid & 3;        // A-fill 16-float segment

    for (int s = 0; s < NSTAGE; s++) {
        const int buf = s & 1;
        __syncthreads();                       // all readers of buf (s+1)&1 done
        if (s < NSTAGE - 1) {
            issue_stage(s + 1);
            asm volatile("cp.async.wait_group 1;" ::: "memory");
        } else {
            asm volatile("cp.async.wait_group 0;" ::: "memory");
        }
        __syncthreads();                       // stage-s cp.async data visible

        // ---- A fill: A[row][k'] = fp16(relu(a_row[kc+k'] + bstage[row][k'])) ----
        {
            const int kc = s * KC;
            const float* bst = (const float*)(smem + SM_BSTG + buf * BS_BYTES)
                               + fr_row * BS_STRF + fr_seg * 16;
            const float* ar = s_arow + kc + fr_seg * 16;
            char* Abuf = smem + SM_A + buf * A_BYTES;
            uint32_t abase = fr_row * (A_STRH * 2) + fr_seg * 32;
            #pragma unroll
            for (int i = 0; i < 4; i++) {
                float4 bv = *(const float4*)(bst + i * 4);
                float4 av = *(const float4*)(ar + i * 4);
                __half2 h0 = __floats2half2_rn(fmaxf(av.x + bv.x, 0.0f),
                                               fmaxf(av.y + bv.y, 0.0f));
                __half2 h1 = __floats2half2_rn(fmaxf(av.z + bv.z, 0.0f),
                                               fmaxf(av.w + bv.w, 0.0f));
                uint2 pack;
                pack.x = *(uint32_t*)&h0;
                pack.y = *(uint32_t*)&h1;
                *(uint2*)(Abuf + abase + i * 8) = pack;
            }
        }
        __syncthreads();                       // A tile ready

        // ---- MMA: 4 k16 steps ----
        const uint32_t Abase = smem_base + SM_A + buf * A_BYTES;
        const uint32_t Bbase = smem_base + SM_B + buf * BB_BYTES;
        #pragma unroll
        for (int kk = 0; kk < 4; kk++) {
            uint32_t afr[2][4];
            #pragma unroll
            for (int mt = 0; mt < 2; mt++) {
                uint32_t addr = Abase + (a_row_base + mt * 16) * (A_STRH * 2)
                              + kk * 32 + a_colb;
                ldm_x4(addr, afr[mt][0], afr[mt][1], afr[mt][2], afr[mt][3]);
            }
            #pragma unroll
            for (int ntp = 0; ntp < 4; ntp++) {
                uint32_t b0, b1, b2r, b3r;
                uint32_t addr = Bbase + (b_row_base + ntp * 16) * (B_STRH * 2)
                              + kk * 32 + b_colb;
                ldm_x4(addr, b0, b1, b2r, b3r);
                #pragma unroll
                for (int mt = 0; mt < 2; mt++) {
                    mma_f16(acc[mt][2 * ntp + 0], afr[mt], b0, b1);
                    mma_f16(acc[mt][2 * ntp + 1], afr[mt], b2r, b3r);
                }
            }
        }
    }

    // ---- epilogue: out[row] = sum_j relu(D[row,j]+b2[j])*w3[j] + b3 ----
    float p[4] = {0.0f, 0.0f, 0.0f, 0.0f};  // rows {g, g+8, g+16, g+24} (warp-local)
    #pragma unroll
    for (int nt = 0; nt < 8; nt++) {
        const int j = wc * 64 + nt * 8 + 2 * tg;
        const float b2a = s_b2[j], b2b = s_b2[j + 1];
        const float w3a = s_w3[j], w3b = s_w3[j + 1];
        #pragma unroll
        for (int mt = 0; mt < 2; mt++) {
            const float* c = acc[mt][nt];
            p[mt * 2 + 0] += fmaxf(c[0] + b2a, 0.0f) * w3a + fmaxf(c[1] + b2b, 0.0f) * w3b;
            p[mt * 2 + 1] += fmaxf(c[2] + b2a, 0.0f) * w3a + fmaxf(c[3] + b2b, 0.0f) * w3b;
        }
    }
    #pragma unroll
    for (int off = 1; off < 4; off <<= 1)
        #pragma unroll
        for (int q = 0; q < 4; q++)
            p[q] += __shfl_xor_sync(0xffffffffu, p[q], off);

    __syncthreads();   // protect s_part (no aliasing issue, but order epilogue)
    if (tg == 0) {
        #pragma unroll
        for (int mt = 0; mt < 2; mt++)
            #pragma unroll
            for (int h = 0; h < 2; h++) {
                int row = wr * 32 + mt * 16 + h * 8 + g;
                s_part[row * 4 + wc] = p[mt * 2 + h];
            }
    }
    __syncthreads();
    if (tid < 128) {
        float v = s_part[tid * 4 + 0] + s_part[tid * 4 + 1]
                + s_part[tid * 4 + 2] + s_part[tid * 4 + 3] + b3[0];
        out[(size_t)(b * N_DIM + n) * M_DIM + m0 + tid] = v;
    }
}

// ============================================================================
// Launch
// ============================================================================
extern "C" void kernel_launch(void* const* d_in, const int* in_sizes, int n_in,
                              void* d_out, int out_size) {
    const float* PhiA = (const float*)d_in[0];
    const float* PhiB = (const float*)d_in[1];
    const float* W1a  = (const float*)d_in[2];
    const float* W1b  = (const float*)d_in[3];
    const float* b1   = (const float*)d_in[4];
    const float* W2   = (const float*)d_in[5];
    const float* b2   = (const float*)d_in[6];
    const float* W3   = (const float*)d_in[7];
    const float* b3   = (const float*)d_in[8];
    float* out = (float*)d_out;

    float *aproj = nullptr, *bproj = nullptr;
    __half* w2h = nullptr;
    cudaGetSymbolAddress((void**)&aproj, g_aproj);
    cudaGetSymbolAddress((void**)&bproj, g_bproj);
    cudaGetSymbolAddress((void**)&w2h, g_w2h);

    // a_proj = Phi_A @ W1a          (2048 x 512, K=576)
    proj_kernel<<<dim3((B_DIM * N_DIM) / 64, H1_DIM / 64), 256>>>(PhiA, W1a, nullptr, aproj);
    // b_proj = Phi_B @ W1b + b1     (512 x 512, K=576)
    proj_kernel<<<dim3((B_DIM * M_DIM) / 64, H1_DIM / 64), 256>>>(PhiB, W1b, b1, bproj);
    // W2H[j][k] = fp16(W2[k][j])
    w2_half_kernel<<<dim3(H1_DIM / 32, H2_DIM / 32), dim3(32, 8)>>>(W2, w2h);

    cudaFuncSetAttribute(pair_mlp_main, cudaFuncAttributeMaxDynamicSharedMemorySize,
                         SMEM_MAIN_TOTAL);
    pair_mlp_main<<<B_DIM * N_DIM * (M_DIM / 128), 512, SMEM_MAIN_TOTAL>>>(
        aproj, bproj, w2h, b2, W3, b3, out);
}

// round 3
// speedup vs baseline: 1.1417x; 1.1417x over previous
#include <cuda_runtime.h>
#include <cuda_fp16.h>
#include <cstdint>

// ============================================================================
// Problem constants
// ============================================================================
#define B_DIM  2
#define N_DIM  1024
#define M_DIM  256
#define D_DIM  576
#define H1_DIM 512
#define H2_DIM 256

// Scratch (allocation-free rule: __device__ globals)
__device__ float  g_aproj[B_DIM * N_DIM * H1_DIM];    // a_proj fp32
__device__ __half g_bprojh[B_DIM * M_DIM * H1_DIM];   // fp16(b_proj + b1)
__device__ uint4  g_w2frag[32 * 16 * 32];             // W2 pre-packed mma B-fragments

// ============================================================================
// PTX helpers (base ISA — harness compiles for compute_103, no 'a' features)
// ============================================================================
__device__ __forceinline__ uint32_t smem_to_u32(const void* p) {
    uint32_t a;
    asm("{ .reg .u64 t; cvta.to.shared.u64 t, %1; cvt.u32.u64 %0, t; }" : "=r"(a) : "l"(p));
    return a;
}

__device__ __forceinline__ void cp16(uint32_t s, const void* g) {
    asm volatile("cp.async.cg.shared.global [%0], [%1], 16;" :: "r"(s), "l"(g) : "memory");
}
__device__ __forceinline__ void cp_commit() {
    asm volatile("cp.async.commit_group;" ::: "memory");
}

__device__ __forceinline__ void mma_f16(float* c, const uint32_t* a, uint32_t b0, uint32_t b1) {
    asm volatile(
        "mma.sync.aligned.m16n8k16.row.col.f32.f16.f16.f32 "
        "{%0,%1,%2,%3}, {%4,%5,%6,%7}, {%8,%9}, {%0,%1,%2,%3};"
        : "+f"(c[0]), "+f"(c[1]), "+f"(c[2]), "+f"(c[3])
        : "r"(a[0]), "r"(a[1]), "r"(a[2]), "r"(a[3]), "r"(b0), "r"(b1));
}

// relu(a + b) packed to half2 (one A-fragment register)
__device__ __forceinline__ uint32_t fragAB(float2 ar, __half2 b) {
    float2 bf = __half22float2(b);
    __half2 h = __floats2half2_rn(fmaxf(ar.x + bf.x, 0.0f), fmaxf(ar.y + bf.y, 0.0f));
    return *(uint32_t*)&h;
}

// ============================================================================
// Prep 1: projection GEMM  out[r, h] = X[r, :576] @ W[:576, h] (+ bias)
// 128x64 tile, BK=16, 256 threads, 8x4 microtile. Optional fp16 output.
// ============================================================================
template <bool HALF_OUT>
__global__ __launch_bounds__(256) void proj_kernel(
    const float* __restrict__ X, const float* __restrict__ W,
    const float* __restrict__ bias, void* __restrict__ out)
{
    __shared__ float As[16][132];
    __shared__ float Bs[16][68];
    const int tid = threadIdx.x;
    const int r0 = blockIdx.x * 128;
    const int c0 = blockIdx.y * 64;
    const int tx = tid & 15;   // 16 col groups of 4
    const int ty = tid >> 4;   // 16 row groups of 8
    float acc[8][4] = {};

    for (int k0 = 0; k0 < D_DIM; k0 += 16) {
        #pragma unroll
        for (int i = 0; i < 8; i++) {
            int idx = tid + i * 256;
            int m = idx >> 4, k = idx & 15;
            As[k][m] = X[(size_t)(r0 + m) * D_DIM + k0 + k];
        }
        #pragma unroll
        for (int i = 0; i < 4; i++) {
            int idx = tid + i * 256;
            int k = idx >> 6, c = idx & 63;
            Bs[k][c] = W[(size_t)(k0 + k) * H1_DIM + c0 + c];
        }
        __syncthreads();
        #pragma unroll
        for (int kk = 0; kk < 16; kk++) {
            float a[8], b[4];
            #pragma unroll
            for (int i = 0; i < 8; i++) a[i] = As[kk][ty * 8 + i];
            #pragma unroll
            for (int j = 0; j < 4; j++) b[j] = Bs[kk][tx * 4 + j];
            #pragma unroll
            for (int i = 0; i < 8; i++)
                #pragma unroll
                for (int j = 0; j < 4; j++) acc[i][j] += a[i] * b[j];
        }
        __syncthreads();
    }
    #pragma unroll
    for (int i = 0; i < 8; i++)
        #pragma unroll
        for (int j = 0; j < 4; j++) {
            int r = r0 + ty * 8 + i, c = c0 + tx * 4 + j;
            float v = acc[i][j] + (bias ? bias[c] : 0.0f);
            if (HALF_OUT)
                ((__half*)out)[(size_t)r * H1_DIM + c] = __float2half_rn(v);
            else
                ((float*)out)[(size_t)r * H1_DIM + c] = v;
        }
}

// ============================================================================
// Prep 2: W2 (512x256 fp32, [k][j]) -> pre-fragmented fp16 mma-B layout.
// w2frag[(kb*16 + jbp)*32 + lane] = uint4 {b0,b1 (j=jbp*16+g), b0,b1 (j+8)}
//   where per m16n8k16 B-frag: b0={W2[k0][j],W2[k0+1][j]}, b1={W2[k0+8][j],+9},
//   k0 = kb*16 + 2*tg, g = lane>>2, tg = lane&3.
// ============================================================================
__global__ void w2frag_kernel(const float* __restrict__ W2, uint4* __restrict__ out) {
    const int kb = blockIdx.x;     // 0..31
    const int jbp = blockIdx.y;    // 0..15
    const int lid = threadIdx.x;   // 0..31
    const int gg = lid >> 2, tg = lid & 3;
    const int k0 = kb * 16 + 2 * tg;
    const int j0 = jbp * 16 + gg;

    auto p2 = [&](int k, int j) {
        __half2 h = __floats2half2_rn(W2[(size_t)k * H2_DIM + j],
                                      W2[(size_t)(k + 1) * H2_DIM + j]);
        return *(uint32_t*)&h;
    };
    uint4 u;
    u.x = p2(k0, j0);
    u.y = p2(k0 + 8, j0);
    u.z = p2(k0, j0 + 8);
    u.w = p2(k0 + 8, j0 + 8);
    out[(kb * 16 + jbp) * 32 + lid] = u;
}

// ============================================================================
// Main fused kernel
//   CTA: 1 n x 128 m x 256 h2. 512 threads, 16 warps (4 m-bands x 4 j-bands),
//   warp tile 32x64. K=512 in 8 stages of 64.
//   B operand: LDG.128 of pre-fragmented W2 straight from L2 (no smem).
//   A operand: bproj fp16 cp.async-staged (pad-72 rows, conflict-free),
//     fragments computed in registers: fp16(relu(arow + bp)). No ldmatrix.
//   Epilogue: relu(+b2) dot w3 fused in registers, shfl+smem reduce.
// ============================================================================
__global__ __launch_bounds__(512, 1) void pair_mlp_main(
    const float* __restrict__ aproj, const __half* __restrict__ bprojh,
    const uint4* __restrict__ w2f, const float* __restrict__ b2,
    const float* __restrict__ w3, const float* __restrict__ b3,
    float* __restrict__ out)
{
    __shared__ float s_arow[H1_DIM];
    __shared__ float s_b2[H2_DIM];
    __shared__ float s_w3[H2_DIM];
    __shared__ float s_part[128 * 4];
    __shared__ __align__(16) __half s_bp[2][128][72];   // 64 data halves + pad

    const int tid = threadIdx.x;
    const int wid = tid >> 5;
    const int lid = tid & 31;
    const int wr  = wid >> 2;   // m band: rows wr*32
    const int wc  = wid & 3;    // j band: cols wc*64
    const int g   = lid >> 2;
    const int tg  = lid & 3;

    const int t  = blockIdx.x;            // 0..4095
    const int b  = t >> 11;
    const int n  = (t >> 1) & (N_DIM - 1);
    const int m0 = (t & 1) * 128;

    if (tid < H1_DIM) s_arow[tid] = aproj[(size_t)(b * N_DIM + n) * H1_DIM + tid];
    if (tid < H2_DIM) { s_b2[tid] = b2[tid]; s_w3[tid] = w3[tid]; }

    const __half* bpg = bprojh + (size_t)(b * M_DIM + m0) * H1_DIM;

    // cp.async: stage s of bproj fp16 (128 rows x 64 halves) into s_bp[s&1]
    auto issue_bp = [&](int s) {
        const int buf = s & 1;
        const int kc = s * 64;
        #pragma unroll
        for (int i = 0; i < 2; i++) {
            int idx = tid + i * 512;          // 0..1023
            int row = idx >> 3, c = idx & 7;  // 8 x 16B per row
            cp16(smem_to_u32(&s_bp[buf][row][c * 8]),
                 bpg + (size_t)row * H1_DIM + kc + c * 8);
        }
        cp_commit();
    };
    issue_bp(0);

    float acc[2][8][4];
    #pragma unroll
    for (int mt = 0; mt < 2; mt++)
        #pragma unroll
        for (int nt = 0; nt < 8; nt++)
            #pragma unroll
            for (int q = 0; q < 4; q++) acc[mt][nt][q] = 0.0f;

    const int arow_base = wr * 32 + g;   // rows: +0, +8, +16, +24

    for (int s = 0; s < 8; s++) {
        const int buf = s & 1;
        const int kc = s * 64;
        __syncthreads();                           // close reads of s_bp[buf^1]
        if (s + 1 < 8) {
            issue_bp(s + 1);
            asm volatile("cp.async.wait_group 1;" ::: "memory");
        } else {
            asm volatile("cp.async.wait_group 0;" ::: "memory");
        }
        __syncthreads();                           // stage-s data visible

        #pragma unroll
        for (int kk = 0; kk < 4; kk++) {
            const int kb = s * 4 + kk;
            // ---- B fragments: LDG.128 from L2 (pre-fragmented W2) ----
            uint4 bf[4];
            #pragma unroll
            for (int p = 0; p < 4; p++)
                bf[p] = w2f[(kb * 16 + wc * 4 + p) * 32 + lid];

            // ---- A fragments in registers: fp16(relu(arow + bp)) ----
            const int k0 = kk * 16 + 2 * tg;
            const float2 ar0 = *(const float2*)&s_arow[kc + k0];
            const float2 ar8 = *(const float2*)&s_arow[kc + k0 + 8];
            uint32_t a0[4], a1[4];
            {
                const __half2 bA0 = *(const __half2*)&s_bp[buf][arow_base +  0][k0];
                const __half2 bB0 = *(const __half2*)&s_bp[buf][arow_base +  8][k0];
                const __half2 bA8 = *(const __half2*)&s_bp[buf][arow_base +  0][k0 + 8];
                const __half2 bB8 = *(const __half2*)&s_bp[buf][arow_base +  8][k0 + 8];
                a0[0] = fragAB(ar0, bA0);
                a0[1] = fragAB(ar0, bB0);
                a0[2] = fragAB(ar8, bA8);
                a0[3] = fragAB(ar8, bB8);
            }
            {
                const __half2 bA0 = *(const __half2*)&s_bp[buf][arow_base + 16][k0];
                const __half2 bB0 = *(const __half2*)&s_bp[buf][arow_base + 24][k0];
                const __half2 bA8 = *(const __half2*)&s_bp[buf][arow_base + 16][k0 + 8];
                const __half2 bB8 = *(const __half2*)&s_bp[buf][arow_base + 24][k0 + 8];
                a1[0] = fragAB(ar0, bA0);
                a1[1] = fragAB(ar0, bB0);
                a1[2] = fragAB(ar8, bA8);
                a1[3] = fragAB(ar8, bB8);
            }

            // ---- 16 MMAs ----
            #pragma unroll
            for (int p = 0; p < 4; p++) {
                mma_f16(acc[0][2 * p + 0], a0, bf[p].x, bf[p].y);
                mma_f16(acc[0][2 * p + 1], a0, bf[p].z, bf[p].w);
                mma_f16(acc[1][2 * p + 0], a1, bf[p].x, bf[p].y);
                mma_f16(acc[1][2 * p + 1], a1, bf[p].z, bf[p].w);
            }
        }
    }

    // ---- epilogue: out[row] = sum_j relu(D[row,j]+b2[j])*w3[j] + b3 ----
    float p[4] = {0.0f, 0.0f, 0.0f, 0.0f};  // rows {g, g+8} x {mt0, mt1}
    #pragma unroll
    for (int nt = 0; nt < 8; nt++) {
        const int j = wc * 64 + nt * 8 + 2 * tg;
        const float b2a = s_b2[j], b2b = s_b2[j + 1];
        const float w3a = s_w3[j], w3b = s_w3[j + 1];
        #pragma unroll
        for (int mt = 0; mt < 2; mt++) {
            const float* c = acc[mt][nt];
            p[mt * 2 + 0] += fmaxf(c[0] + b2a, 0.0f) * w3a + fmaxf(c[1] + b2b, 0.0f) * w3b;
            p[mt * 2 + 1] += fmaxf(c[2] + b2a, 0.0f) * w3a + fmaxf(c[3] + b2b, 0.0f) * w3b;
        }
    }
    #pragma unroll
    for (int off = 1; off < 4; off <<= 1)
        #pragma unroll
        for (int q = 0; q < 4; q++)
            p[q] += __shfl_xor_sync(0xffffffffu, p[q], off);

    __syncthreads();
    if (tg == 0) {
        #pragma unroll
        for (int mt = 0; mt < 2; mt++)
            #pragma unroll
            for (int h = 0; h < 2; h++) {
                int row = wr * 32 + mt * 16 + h * 8 + g;
                s_part[row * 4 + wc] = p[mt * 2 + h];
            }
    }
    __syncthreads();
    if (tid < 128) {
        float v = s_part[tid * 4 + 0] + s_part[tid * 4 + 1]
                + s_part[tid * 4 + 2] + s_part[tid * 4 + 3] + b3[0];
        out[(size_t)(b * N_DIM + n) * M_DIM + m0 + tid] = v;
    }
}

// ============================================================================
// Launch
// ============================================================================
extern "C" void kernel_launch(void* const* d_in, const int* in_sizes, int n_in,
                              void* d_out, int out_size) {
    const float* PhiA = (const float*)d_in[0];
    const float* PhiB = (const float*)d_in[1];
    const float* W1a  = (const float*)d_in[2];
    const float* W1b  = (const float*)d_in[3];
    const float* b1   = (const float*)d_in[4];
    const float* W2   = (const float*)d_in[5];
    const float* b2   = (const float*)d_in[6];
    const float* W3   = (const float*)d_in[7];
    const float* b3   = (const float*)d_in[8];
    float* out = (float*)d_out;

    float* aproj = nullptr;
    __half* bprojh = nullptr;
    uint4* w2f = nullptr;
    cudaGetSymbolAddress((void**)&aproj, g_aproj);
    cudaGetSymbolAddress((void**)&bprojh, g_bprojh);
    cudaGetSymbolAddress((void**)&w2f, g_w2frag);

    // a_proj = Phi_A @ W1a                    (2048 x 512, K=576, fp32 out)
    proj_kernel<false><<<dim3((B_DIM * N_DIM) / 128, H1_DIM / 64), 256>>>(
        PhiA, W1a, nullptr, aproj);
    // b_proj = fp16(Phi_B @ W1b + b1)         (512 x 512, K=576, fp16 out)
    proj_kernel<true><<<dim3((B_DIM * M_DIM) / 128, H1_DIM / 64), 256>>>(
        PhiB, W1b, b1, bprojh);
    // W2 -> pre-fragmented fp16 B-operand layout
    w2frag_kernel<<<dim3(32, 16), 32>>>(W2, w2f);

    pair_mlp_main<<<B_DIM * N_DIM * (M_DIM / 128), 512>>>(
        aproj, bprojh, w2f, b2, W3, b3, out);
}

// round 6
// speedup vs baseline: 1.3117x; 1.1488x over previous
#include <cuda_runtime.h>
#include <cuda_fp16.h>
#include <cstdint>

// ============================================================================
// Problem constants
// ============================================================================
#define B_DIM  2
#define N_DIM  1024
#define M_DIM  256
#define D_DIM  576
#define H1_DIM 512
#define H2_DIM 256

// Scratch (allocation-free rule: __device__ globals)
__device__ __half g_aprojh[B_DIM * N_DIM * H1_DIM];   // fp16(a_proj)
__device__ __half g_bprojh[B_DIM * M_DIM * H1_DIM];   // fp16(b_proj + b1)
__device__ uint4  g_w2frag[32 * 16 * 32];             // W2 pre-packed mma B-fragments

// ============================================================================
// PTX helpers (base ISA — harness compiles for compute_103, no 'a' features)
// ============================================================================
__device__ __forceinline__ uint32_t smem_to_u32(const void* p) {
    uint32_t a;
    asm("{ .reg .u64 t; cvta.to.shared.u64 t, %1; cvt.u32.u64 %0, t; }" : "=r"(a) : "l"(p));
    return a;
}

__device__ __forceinline__ void cp16(uint32_t s, const void* g) {
    asm volatile("cp.async.cg.shared.global [%0], [%1], 16;" :: "r"(s), "l"(g) : "memory");
}
__device__ __forceinline__ void cp_commit() {
    asm volatile("cp.async.commit_group;" ::: "memory");
}

__device__ __forceinline__ void mma_f16(float* c, const uint32_t* a, uint32_t b0, uint32_t b1) {
    asm volatile(
        "mma.sync.aligned.m16n8k16.row.col.f32.f16.f16.f32 "
        "{%0,%1,%2,%3}, {%4,%5,%6,%7}, {%8,%9}, {%0,%1,%2,%3};"
        : "+f"(c[0]), "+f"(c[1]), "+f"(c[2]), "+f"(c[3])
        : "r"(a[0]), "r"(a[1]), "r"(a[2]), "r"(a[3]), "r"(b0), "r"(b1));
}

// h1 fragment: fp16 relu(a + b), 2 ops (HADD2 + HMAX2)
__device__ __forceinline__ uint32_t fragAB(__half2 a, __half2 b) {
    __half2 z = __float2half2_rn(0.0f);
    __half2 h = __hmax2(__hadd2(a, b), z);
    return *(uint32_t*)&h;
}

// ============================================================================
// Prep 1 (merged): both projection GEMMs, fp16 output.
//   blockIdx.x <  32 : a_proj tile rows (2048 rows)
//   blockIdx.x >= 32 : b_proj tile rows (512 rows, + b1)
// 64x64 tile, BK=16, 256 threads, 4x4 microtile.
// ============================================================================
__global__ __launch_bounds__(256) void proj_both_kernel(
    const float* __restrict__ PhiA, const float* __restrict__ PhiB,
    const float* __restrict__ W1a, const float* __restrict__ W1b,
    const float* __restrict__ b1,
    __half* __restrict__ aout, __half* __restrict__ bout)
{
    __shared__ float As[16][65];
    __shared__ float Bs[16][65];
    const int bx = blockIdx.x;
    const bool isB = bx >= 32;
    const float* X = isB ? PhiB : PhiA;
    const float* W = isB ? W1b : W1a;
    const float* bias = isB ? b1 : nullptr;
    __half* out = isB ? bout : aout;
    const int r0 = (isB ? bx - 32 : bx) * 64;
    const int c0 = blockIdx.y * 64;

    const int tid = threadIdx.x;
    const int tx = tid & 15;
    const int ty = tid >> 4;
    float acc[4][4] = {};

    for (int k0 = 0; k0 < D_DIM; k0 += 16) {
        #pragma unroll
        for (int i = 0; i < 4; i++) {
            int idx = tid + i * 256;
            int m = idx >> 4, k = idx & 15;
            As[k][m] = X[(size_t)(r0 + m) * D_DIM + k0 + k];
        }
        #pragma unroll
        for (int i = 0; i < 4; i++) {
            int idx = tid + i * 256;
            int k = idx >> 6, c = idx & 63;
            Bs[k][c] = W[(size_t)(k0 + k) * H1_DIM + c0 + c];
        }
        __syncthreads();
        #pragma unroll
        for (int kk = 0; kk < 16; kk++) {
            float a[4], b[4];
            #pragma unroll
            for (int i = 0; i < 4; i++) a[i] = As[kk][ty * 4 + i];
            #pragma unroll
            for (int j = 0; j < 4; j++) b[j] = Bs[kk][tx * 4 + j];
            #pragma unroll
            for (int i = 0; i < 4; i++)
                #pragma unroll
                for (int j = 0; j < 4; j++) acc[i][j] += a[i] * b[j];
        }
        __syncthreads();
    }
    #pragma unroll
    for (int i = 0; i < 4; i++)
        #pragma unroll
        for (int j = 0; j < 4; j++) {
            int r = r0 + ty * 4 + i, c = c0 + tx * 4 + j;
            float v = acc[i][j] + (bias ? bias[c] : 0.0f);
            out[(size_t)r * H1_DIM + c] = __float2half_rn(v);
        }
}

// ============================================================================
// Prep 2: W2 (512x256 fp32, [k][j]) -> pre-fragmented fp16 mma-B layout.
// w2frag[(kb*16 + jbp)*32 + lane] = uint4 {b0,b1 (j=jbp*16+g), b0,b1 (j+8)}
// ============================================================================
__global__ void w2frag_kernel(const float* __restrict__ W2, uint4* __restrict__ out) {
    const int kb = blockIdx.x;     // 0..31
    const int jbp = blockIdx.y;    // 0..15
    const int lid = threadIdx.x;   // 0..31
    const int gg = lid >> 2, tg = lid & 3;
    const int k0 = kb * 16 + 2 * tg;
    const int j0 = jbp * 16 + gg;

    auto p2 = [&](int k, int j) {
        __half2 h = __floats2half2_rn(W2[(size_t)k * H2_DIM + j],
                                      W2[(size_t)(k + 1) * H2_DIM + j]);
        return *(uint32_t*)&h;
    };
    uint4 u;
    u.x = p2(k0, j0);
    u.y = p2(k0 + 8, j0);
    u.z = p2(k0, j0 + 8);
    u.w = p2(k0 + 8, j0 + 8);
    out[(kb * 16 + jbp) * 32 + lid] = u;
}

// ============================================================================
// Main fused kernel
//   CTA: 1 n x 128 m x 256 h2. 512 threads, 16 warps = 8 m-bands x 2 j-bands,
//   warp tile 16m x 128j. K=512 in 8 stages of 64.
//   B: LDG.128 of pre-fragmented W2 from L2 (no smem).
//   A: bproj fp16 cp.async-staged; fragments = HADD2+HMAX2 in registers
//      against the fp16 a-row (broadcast from smem). No ldmatrix.
//   Epilogue: relu(+b2) dot w3 in registers, shfl + smem reduce, one store.
// ============================================================================
__global__ __launch_bounds__(512, 1) void pair_mlp_main(
    const __half* __restrict__ aprojh, const __half* __restrict__ bprojh,
    const uint4* __restrict__ w2f, const float* __restrict__ b2,
    const float* __restrict__ w3, const float* __restrict__ b3,
    float* __restrict__ out)
{
    __shared__ __align__(4) __half s_arowh[H1_DIM];
    __shared__ float s_b2[H2_DIM];
    __shared__ float s_w3[H2_DIM];
    __shared__ float s_part[128 * 2];
    __shared__ __align__(16) __half s_bp[2][128][72];   // 64 data halves + pad

    const int tid = threadIdx.x;
    const int wid = tid >> 5;
    const int lid = tid & 31;
    const int wr  = wid >> 1;   // m band: rows wr*16
    const int wc  = wid & 1;    // j band: cols wc*128
    const int g   = lid >> 2;
    const int tg  = lid & 3;

    const int t  = blockIdx.x;            // 0..4095
    const int b  = t >> 11;
    const int n  = (t >> 1) & (N_DIM - 1);
    const int m0 = (t & 1) * 128;

    if (tid < H1_DIM / 2)
        ((uint32_t*)s_arowh)[tid] =
            ((const uint32_t*)(aprojh + (size_t)(b * N_DIM + n) * H1_DIM))[tid];
    if (tid < H2_DIM) { s_b2[tid] = b2[tid]; s_w3[tid] = w3[tid]; }

    const __half* bpg = bprojh + (size_t)(b * M_DIM + m0) * H1_DIM;

    // cp.async: stage s of bproj fp16 (128 rows x 64 halves) into s_bp[s&1]
    auto issue_bp = [&](int s) {
        const int buf = s & 1;
        const int kc = s * 64;
        #pragma unroll
        for (int i = 0; i < 2; i++) {
            int idx = tid + i * 512;          // 0..1023
            int row = idx >> 3, c = idx & 7;  // 8 x 16B per row
            cp16(smem_to_u32(&s_bp[buf][row][c * 8]),
                 bpg + (size_t)row * H1_DIM + kc + c * 8);
        }
        cp_commit();
    };
    issue_bp(0);

    float acc[16][4];
    #pragma unroll
    for (int nt = 0; nt < 16; nt++)
        #pragma unroll
        for (int q = 0; q < 4; q++) acc[nt][q] = 0.0f;

    const int r0 = wr * 16 + g;   // A rows: r0, r0+8

    for (int s = 0; s < 8; s++) {
        const int buf = s & 1;
        const int kc = s * 64;
        __syncthreads();                           // close reads of s_bp[buf^1]
        if (s + 1 < 8) {
            issue_bp(s + 1);
            asm volatile("cp.async.wait_group 1;" ::: "memory");
        } else {
            asm volatile("cp.async.wait_group 0;" ::: "memory");
        }
        __syncthreads();                           // stage-s data visible

        #pragma unroll
        for (int kk = 0; kk < 4; kk++) {
            const int kb = s * 4 + kk;
            const int fb = (kb * 16 + wc * 8) * 32 + lid;
            // ---- first half of B fragments (j: wc*128 .. +63) ----
            uint4 bf0[4];
            #pragma unroll
            for (int p = 0; p < 4; p++) bf0[p] = w2f[fb + p * 32];

            // ---- A fragments: fp16 relu(arow + bp), 2 ops each ----
            const int k0 = kk * 16 + 2 * tg;
            const __half2 a0h = *(const __half2*)&s_arowh[kc + k0];
            const __half2 a8h = *(const __half2*)&s_arowh[kc + k0 + 8];
            uint32_t a[4];
            a[0] = fragAB(a0h, *(const __half2*)&s_bp[buf][r0    ][k0]);
            a[1] = fragAB(a0h, *(const __half2*)&s_bp[buf][r0 + 8][k0]);
            a[2] = fragAB(a8h, *(const __half2*)&s_bp[buf][r0    ][k0 + 8]);
            a[3] = fragAB(a8h, *(const __half2*)&s_bp[buf][r0 + 8][k0 + 8]);

            // ---- second half of B fragments (j: wc*128+64 .. +127) ----
            uint4 bf1[4];
            #pragma unroll
            for (int p = 0; p < 4; p++) bf1[p] = w2f[fb + (4 + p) * 32];

            #pragma unroll
            for (int p = 0; p < 4; p++) {
                mma_f16(acc[2 * p + 0], a, bf0[p].x, bf0[p].y);
                mma_f16(acc[2 * p + 1], a, bf0[p].z, bf0[p].w);
            }
            #pragma unroll
            for (int p = 0; p < 4; p++) {
                mma_f16(acc[8 + 2 * p + 0], a, bf1[p].x, bf1[p].y);
                mma_f16(acc[8 + 2 * p + 1], a, bf1[p].z, bf1[p].w);
            }
        }
    }

    // ---- epilogue: out[row] = sum_j relu(D[row,j]+b2[j])*w3[j] + b3 ----
    float p0 = 0.0f, p1 = 0.0f;   // rows r0, r0+8
    #pragma unroll
    for (int nt = 0; nt < 16; nt++) {
        const int j = wc * 128 + nt * 8 + 2 * tg;
        const float b2a = s_b2[j], b2b = s_b2[j + 1];
        const float w3a = s_w3[j], w3b = s_w3[j + 1];
        const float* c = acc[nt];
        p0 += fmaxf(c[0] + b2a, 0.0f) * w3a + fmaxf(c[1] + b2b, 0.0f) * w3b;
        p1 += fmaxf(c[2] + b2a, 0.0f) * w3a + fmaxf(c[3] + b2b, 0.0f) * w3b;
    }
    #pragma unroll
    for (int off = 1; off < 4; off <<= 1) {
        p0 += __shfl_xor_sync(0xffffffffu, p0, off);
        p1 += __shfl_xor_sync(0xffffffffu, p1, off);
    }

    __syncthreads();
    if (tg == 0) {
        s_part[(wr * 16 + g) * 2 + wc] = p0;
        s_part[(wr * 16 + 8 + g) * 2 + wc] = p1;
    }
    __syncthreads();
    if (tid < 128) {
        float v = s_part[tid * 2 + 0] + s_part[tid * 2 + 1] + b3[0];
        out[(size_t)(b * N_DIM + n) * M_DIM + m0 + tid] = v;
    }
}

// ============================================================================
// Launch
// ============================================================================
extern "C" void kernel_launch(void* const* d_in, const int* in_sizes, int n_in,
                              void* d_out, int out_size) {
    const float* PhiA = (const float*)d_in[0];
    const float* PhiB = (const float*)d_in[1];
    const float* W1a  = (const float*)d_in[2];
    const float* W1b  = (const float*)d_in[3];
    const float* b1   = (const float*)d_in[4];
    const float* W2   = (const float*)d_in[5];
    const float* b2   = (const float*)d_in[6];
    const float* W3   = (const float*)d_in[7];
    const float* b3   = (const float*)d_in[8];
    float* out = (float*)d_out;

    __half* aprojh = nullptr;
    __half* bprojh = nullptr;
    uint4* w2f = nullptr;
    cudaGetSymbolAddress((void**)&aprojh, g_aprojh);
    cudaGetSymbolAddress((void**)&bprojh, g_bprojh);
    cudaGetSymbolAddress((void**)&w2f, g_w2frag);

    // both projections in one launch (A: 32 row-tiles, B: 8 row-tiles)
    proj_both_kernel<<<dim3(40, H1_DIM / 64), 256>>>(
        PhiA, PhiB, W1a, W1b, b1, aprojh, bprojh);
    // W2 -> pre-fragmented fp16 B-operand layout
    w2frag_kernel<<<dim3(32, 16), 32>>>(W2, w2f);

    pair_mlp_main<<<B_DIM * N_DIM * (M_DIM / 128), 512>>>(
        aprojh, bprojh, w2f, b2, W3, b3, out);
}

// round 7
// speedup vs baseline: 1.4389x; 1.0970x over previous
#include <cuda_runtime.h>
#include <cuda_fp16.h>
#include <cstdint>

// ============================================================================
// Problem constants
// ============================================================================
#define B_DIM  2
#define N_DIM  1024
#define M_DIM  256
#define D_DIM  576
#define H1_DIM 512
#define H2_DIM 256

// Scratch (allocation-free rule: __device__ globals)
__device__ __half g_aprojh[B_DIM * N_DIM * H1_DIM];   // fp16(a_proj)
__device__ __half g_bprojh[B_DIM * M_DIM * H1_DIM];   // fp16(b_proj + b1)
__device__ uint4  g_w2frag[32 * 16 * 32];             // W2 pre-packed mma B-fragments

// ============================================================================
// PTX helpers (base ISA — harness compiles for compute_103, no 'a' features)
// ============================================================================
__device__ __forceinline__ uint32_t smem_to_u32(const void* p) {
    uint32_t a;
    asm("{ .reg .u64 t; cvta.to.shared.u64 t, %1; cvt.u32.u64 %0, t; }" : "=r"(a) : "l"(p));
    return a;
}

__device__ __forceinline__ void cp16(uint32_t s, const void* g) {
    asm volatile("cp.async.cg.shared.global [%0], [%1], 16;" :: "r"(s), "l"(g) : "memory");
}
__device__ __forceinline__ void cp_commit() {
    asm volatile("cp.async.commit_group;" ::: "memory");
}

__device__ __forceinline__ void mma_f16(float* c, const uint32_t* a, uint32_t b0, uint32_t b1) {
    asm volatile(
        "mma.sync.aligned.m16n8k16.row.col.f32.f16.f16.f32 "
        "{%0,%1,%2,%3}, {%4,%5,%6,%7}, {%8,%9}, {%0,%1,%2,%3};"
        : "+f"(c[0]), "+f"(c[1]), "+f"(c[2]), "+f"(c[3])
        : "r"(a[0]), "r"(a[1]), "r"(a[2]), "r"(a[3]), "r"(b0), "r"(b1));
}

// h1 fragment: fp16 relu(a + b), 2 ops (HADD2 + HMAX2)
__device__ __forceinline__ uint32_t fragAB(__half2 a, __half2 b) {
    __half2 z = __float2half2_rn(0.0f);
    __half2 h = __hmax2(__hadd2(a, b), z);
    return *(uint32_t*)&h;
}

// ============================================================================
// Prep 1 (merged): both projection GEMMs, fp16 output.
//   blockIdx.x <  16 : a_proj tile rows (2048 rows)
//   blockIdx.x >= 16 : b_proj tile rows (512 rows, + b1)
// 128x64 tile, BK=16, 256 threads, 8x4 microtile.
// ============================================================================
__global__ __launch_bounds__(256) void proj_both_kernel(
    const float* __restrict__ PhiA, const float* __restrict__ PhiB,
    const float* __restrict__ W1a, const float* __restrict__ W1b,
    const float* __restrict__ b1,
    __half* __restrict__ aout, __half* __restrict__ bout)
{
    __shared__ float As[16][132];
    __shared__ float Bs[16][68];
    const int bx = blockIdx.x;
    const bool isB = bx >= 16;
    const float* X = isB ? PhiB : PhiA;
    const float* W = isB ? W1b : W1a;
    const float* bias = isB ? b1 : nullptr;
    __half* out = isB ? bout : aout;
    const int r0 = (isB ? bx - 16 : bx) * 128;
    const int c0 = blockIdx.y * 64;

    const int tid = threadIdx.x;
    const int tx = tid & 15;   // col group of 4
    const int ty = tid >> 4;   // row group of 8
    float acc[8][4] = {};

    for (int k0 = 0; k0 < D_DIM; k0 += 16) {
        #pragma unroll
        for (int i = 0; i < 8; i++) {
            int idx = tid + i * 256;
            int m = idx >> 4, k = idx & 15;
            As[k][m] = X[(size_t)(r0 + m) * D_DIM + k0 + k];
        }
        #pragma unroll
        for (int i = 0; i < 4; i++) {
            int idx = tid + i * 256;
            int k = idx >> 6, c = idx & 63;
            Bs[k][c] = W[(size_t)(k0 + k) * H1_DIM + c0 + c];
        }
        __syncthreads();
        #pragma unroll
        for (int kk = 0; kk < 16; kk++) {
            float a[8], b[4];
            *(float4*)&a[0] = *(const float4*)&As[kk][ty * 8];
            *(float4*)&a[4] = *(const float4*)&As[kk][ty * 8 + 4];
            *(float4*)&b[0] = *(const float4*)&Bs[kk][tx * 4];
            #pragma unroll
            for (int i = 0; i < 8; i++)
                #pragma unroll
                for (int j = 0; j < 4; j++) acc[i][j] += a[i] * b[j];
        }
        __syncthreads();
    }
    #pragma unroll
    for (int i = 0; i < 8; i++) {
        const int r = r0 + ty * 8 + i, c = c0 + tx * 4;
        float v0 = acc[i][0], v1 = acc[i][1], v2 = acc[i][2], v3 = acc[i][3];
        if (bias) { v0 += bias[c]; v1 += bias[c + 1]; v2 += bias[c + 2]; v3 += bias[c + 3]; }
        __half2 h01 = __floats2half2_rn(v0, v1);
        __half2 h23 = __floats2half2_rn(v2, v3);
        uint2 u;
        u.x = *(uint32_t*)&h01;
        u.y = *(uint32_t*)&h23;
        *(uint2*)&out[(size_t)r * H1_DIM + c] = u;
    }
}

// ============================================================================
// Prep 2: W2 (512x256 fp32, [k][j]) -> pre-fragmented fp16 mma-B layout.
// w2frag[(kb*16 + jbp)*32 + lane] = uint4 {b0,b1 (j=jbp*16+g), b0,b1 (j+8)}
// ============================================================================
__global__ void w2frag_kernel(const float* __restrict__ W2, uint4* __restrict__ out) {
    const int kb = blockIdx.x;     // 0..31
    const int jbp = blockIdx.y;    // 0..15
    const int lid = threadIdx.x;   // 0..31
    const int gg = lid >> 2, tg = lid & 3;
    const int k0 = kb * 16 + 2 * tg;
    const int j0 = jbp * 16 + gg;

    auto p2 = [&](int k, int j) {
        __half2 h = __floats2half2_rn(W2[(size_t)k * H2_DIM + j],
                                      W2[(size_t)(k + 1) * H2_DIM + j]);
        return *(uint32_t*)&h;
    };
    uint4 u;
    u.x = p2(k0, j0);
    u.y = p2(k0 + 8, j0);
    u.z = p2(k0, j0 + 8);
    u.w = p2(k0 + 8, j0 + 8);
    out[(kb * 16 + jbp) * 32 + lid] = u;
}

// ============================================================================
// Main fused kernel
//   CTA: 1 n x 128 m x 256 h2. 256 threads, 8 warps = 4 m-bands x 2 j-bands,
//   warp tile 32m x 128j. K=512 in 8 stages of 64.
//   B: LDG.128 of pre-fragmented W2 from L2/L1, double-buffered in registers
//      (prefetched one k16-slice ahead -> latency fully pipelined).
//   A: bproj fp16 cp.async-staged; fragments = HADD2+HMAX2 in registers.
//   Epilogue: relu(+b2) dot w3 in registers, shfl + smem reduce, one store.
// ============================================================================
__global__ __launch_bounds__(256, 1) void pair_mlp_main(
    const __half* __restrict__ aprojh, const __half* __restrict__ bprojh,
    const uint4* __restrict__ w2f, const float* __restrict__ b2,
    const float* __restrict__ w3, const float* __restrict__ b3,
    float* __restrict__ out)
{
    __shared__ __align__(4) __half s_arowh[H1_DIM];
    __shared__ float s_b2[H2_DIM];
    __shared__ float s_w3[H2_DIM];
    __shared__ float s_part[128 * 2];
    __shared__ __align__(16) __half s_bp[2][128][72];   // 64 data halves + pad

    const int tid = threadIdx.x;
    const int wid = tid >> 5;
    const int lid = tid & 31;
    const int wr  = wid >> 1;   // m band: rows wr*32
    const int wc  = wid & 1;    // j band: cols wc*128
    const int g   = lid >> 2;
    const int tg  = lid & 3;

    const int t  = blockIdx.x;            // 0..4095
    const int b  = t >> 11;
    const int n  = (t >> 1) & (N_DIM - 1);
    const int m0 = (t & 1) * 128;

    if (tid < H1_DIM / 2)
        ((uint32_t*)s_arowh)[tid] =
            ((const uint32_t*)(aprojh + (size_t)(b * N_DIM + n) * H1_DIM))[tid];
    if (tid < H2_DIM) { s_b2[tid] = b2[tid]; s_w3[tid] = w3[tid]; }

    const __half* bpg = bprojh + (size_t)(b * M_DIM + m0) * H1_DIM;

    // cp.async: stage s of bproj fp16 (128 rows x 64 halves) into s_bp[s&1]
    auto issue_bp = [&](int s) {
        const int buf = s & 1;
        const int kc = s * 64;
        #pragma unroll
        for (int i = 0; i < 4; i++) {
            int idx = tid + i * 256;          // 0..1023
            int row = idx >> 3, c = idx & 7;  // 8 x 16B per row
            cp16(smem_to_u32(&s_bp[buf][row][c * 8]),
                 bpg + (size_t)row * H1_DIM + kc + c * 8);
        }
        cp_commit();
    };
    issue_bp(0);

    float acc[2][16][4];
    #pragma unroll
    for (int mt = 0; mt < 2; mt++)
        #pragma unroll
        for (int nt = 0; nt < 16; nt++)
            #pragma unroll
            for (int q = 0; q < 4; q++) acc[mt][nt][q] = 0.0f;

    const int r0 = wr * 32 + g;   // warp rows: r0, r0+8, r0+16, r0+24

    // B-fragment register double buffer, prefetched by global k16-slice kb
    uint4 bfa[8], bfb[8];
    auto ldB = [&](uint4* dst, int kb) {
        const int fb = (kb * 16 + wc * 8) * 32 + lid;
        #pragma unroll
        for (int p = 0; p < 8; p++) dst[p] = w2f[fb + p * 32];
    };
    ldB(bfa, 0);

    for (int s = 0; s < 8; s++) {
        const int buf = s & 1;
        const int kc = s * 64;
        __syncthreads();                           // close reads of s_bp[buf^1]
        if (s + 1 < 8) {
            issue_bp(s + 1);
            asm volatile("cp.async.wait_group 1;" ::: "memory");
        } else {
            asm volatile("cp.async.wait_group 0;" ::: "memory");
        }
        __syncthreads();                           // stage-s data visible

        #pragma unroll
        for (int kk = 0; kk < 4; kk++) {
            const int kb = s * 4 + kk;
            uint4* cur = (kb & 1) ? bfb : bfa;
            uint4* nxt = (kb & 1) ? bfa : bfb;
            if (kb < 31) ldB(nxt, kb + 1);         // prefetch next slice

            // ---- A fragments: fp16 relu(arow + bp), 2 ops each ----
            const int k0 = kk * 16 + 2 * tg;
            const __half2 a0h = *(const __half2*)&s_arowh[kc + k0];
            const __half2 a8h = *(const __half2*)&s_arowh[kc + k0 + 8];
            uint32_t a0[4], a1[4];
            a0[0] = fragAB(a0h, *(const __half2*)&s_bp[buf][r0     ][k0]);
            a0[1] = fragAB(a0h, *(const __half2*)&s_bp[buf][r0 +  8][k0]);
            a0[2] = fragAB(a8h, *(const __half2*)&s_bp[buf][r0     ][k0 + 8]);
            a0[3] = fragAB(a8h, *(const __half2*)&s_bp[buf][r0 +  8][k0 + 8]);
            a1[0] = fragAB(a0h, *(const __half2*)&s_bp[buf][r0 + 16][k0]);
            a1[1] = fragAB(a0h, *(const __half2*)&s_bp[buf][r0 + 24][k0]);
            a1[2] = fragAB(a8h, *(const __half2*)&s_bp[buf][r0 + 16][k0 + 8]);
            a1[3] = fragAB(a8h, *(const __half2*)&s_bp[buf][r0 + 24][k0 + 8]);

            // ---- 32 MMAs on the current B slice ----
            #pragma unroll
            for (int p = 0; p < 8; p++) {
                mma_f16(acc[0][2 * p + 0], a0, cur[p].x, cur[p].y);
                mma_f16(acc[0][2 * p + 1], a0, cur[p].z, cur[p].w);
                mma_f16(acc[1][2 * p + 0], a1, cur[p].x, cur[p].y);
                mma_f16(acc[1][2 * p + 1], a1, cur[p].z, cur[p].w);
            }
        }
    }

    // ---- epilogue: out[row] = sum_j relu(D[row,j]+b2[j])*w3[j] + b3 ----
    float p0 = 0.0f, p1 = 0.0f, p2s = 0.0f, p3s = 0.0f;  // rows r0,+8,+16,+24
    #pragma unroll
    for (int nt = 0; nt < 16; nt++) {
        const int j = wc * 128 + nt * 8 + 2 * tg;
        const float b2a = s_b2[j], b2b = s_b2[j + 1];
        const float w3a = s_w3[j], w3b = s_w3[j + 1];
        const float* c0 = acc[0][nt];
        const float* c1 = acc[1][nt];
        p0  += fmaxf(c0[0] + b2a, 0.0f) * w3a + fmaxf(c0[1] + b2b, 0.0f) * w3b;
        p1  += fmaxf(c0[2] + b2a, 0.0f) * w3a + fmaxf(c0[3] + b2b, 0.0f) * w3b;
        p2s += fmaxf(c1[0] + b2a, 0.0f) * w3a + fmaxf(c1[1] + b2b, 0.0f) * w3b;
        p3s += fmaxf(c1[2] + b2a, 0.0f) * w3a + fmaxf(c1[3] + b2b, 0.0f) * w3b;
    }
    #pragma unroll
    for (int off = 1; off < 4; off <<= 1) {
        p0  += __shfl_xor_sync(0xffffffffu, p0, off);
        p1  += __shfl_xor_sync(0xffffffffu, p1, off);
        p2s += __shfl_xor_sync(0xffffffffu, p2s, off);
        p3s += __shfl_xor_sync(0xffffffffu, p3s, off);
    }

    __syncthreads();
    if (tg == 0) {
        s_part[(r0     ) * 2 + wc] = p0;
        s_part[(r0 +  8) * 2 + wc] = p1;
        s_part[(r0 + 16) * 2 + wc] = p2s;
        s_part[(r0 + 24) * 2 + wc] = p3s;
    }
    __syncthreads();
    if (tid < 128) {
        float v = s_part[tid * 2 + 0] + s_part[tid * 2 + 1] + b3[0];
        out[(size_t)(b * N_DIM + n) * M_DIM + m0 + tid] = v;
    }
}

// ============================================================================
// Launch
// ============================================================================
extern "C" void kernel_launch(void* const* d_in, const int* in_sizes, int n_in,
                              void* d_out, int out_size) {
    const float* PhiA = (const float*)d_in[0];
    const float* PhiB = (const float*)d_in[1];
    const float* W1a  = (const float*)d_in[2];
    const float* W1b  = (const float*)d_in[3];
    const float* b1   = (const float*)d_in[4];
    const float* W2   = (const float*)d_in[5];
    const float* b2   = (const float*)d_in[6];
    const float* W3   = (const float*)d_in[7];
    const float* b3   = (const float*)d_in[8];
    float* out = (float*)d_out;

    __half* aprojh = nullptr;
    __half* bprojh = nullptr;
    uint4* w2f = nullptr;
    cudaGetSymbolAddress((void**)&aprojh, g_aprojh);
    cudaGetSymbolAddress((void**)&bprojh, g_bprojh);
    cudaGetSymbolAddress((void**)&w2f, g_w2frag);

    // both projections in one launch (A: 16 row-tiles, B: 4 row-tiles)
    proj_both_kernel<<<dim3(20, H1_DIM / 64), 256>>>(
        PhiA, PhiB, W1a, W1b, b1, aprojh, bprojh);
    // W2 -> pre-fragmented fp16 B-operand layout
    w2frag_kernel<<<dim3(32, 16), 32>>>(W2, w2f);

    pair_mlp_main<<<B_DIM * N_DIM * (M_DIM / 128), 256>>>(
        aprojh, bprojh, w2f, b2, W3, b3, out);
}

// round 8
// speedup vs baseline: 1.7015x; 1.1825x over previous
#include <cuda_runtime.h>
#include <cuda_fp16.h>
#include <cstdint>

// ============================================================================
// Problem constants
// ============================================================================
#define B_DIM  2
#define N_DIM  1024
#define M_DIM  256
#define D_DIM  576
#define H1_DIM 512
#define H2_DIM 256

// Scratch (allocation-free rule: __device__ globals)
__device__ __half g_aprojh[B_DIM * N_DIM * H1_DIM];   // fp16(a_proj)
__device__ __half g_bprojh[B_DIM * M_DIM * H1_DIM];   // fp16(b_proj + b1)
__device__ uint4  g_w2frag[32 * 16 * 32];             // W2 pre-packed mma B-fragments

// ============================================================================
// PTX helpers (base ISA — harness compiles for compute_103, no 'a' features)
// ============================================================================
__device__ __forceinline__ uint32_t smem_to_u32(const void* p) {
    uint32_t a;
    asm("{ .reg .u64 t; cvta.to.shared.u64 t, %1; cvt.u32.u64 %0, t; }" : "=r"(a) : "l"(p));
    return a;
}

__device__ __forceinline__ void cp16(uint32_t s, const void* g) {
    asm volatile("cp.async.cg.shared.global [%0], [%1], 16;" :: "r"(s), "l"(g) : "memory");
}
__device__ __forceinline__ void cp_commit() {
    asm volatile("cp.async.commit_group;" ::: "memory");
}

__device__ __forceinline__ void mma_f16(float* c, const uint32_t* a, uint32_t b0, uint32_t b1) {
    asm volatile(
        "mma.sync.aligned.m16n8k16.row.col.f32.f16.f16.f32 "
        "{%0,%1,%2,%3}, {%4,%5,%6,%7}, {%8,%9}, {%0,%1,%2,%3};"
        : "+f"(c[0]), "+f"(c[1]), "+f"(c[2]), "+f"(c[3])
        : "r"(a[0]), "r"(a[1]), "r"(a[2]), "r"(a[3]), "r"(b0), "r"(b1));
}

// h1 fragment: fp16 relu(a + b), 2 ops (HADD2 + HMAX2)
__device__ __forceinline__ uint32_t fragAB(__half2 a, __half2 b) {
    __half2 z = __float2half2_rn(0.0f);
    __half2 h = __hmax2(__hadd2(a, b), z);
    return *(uint32_t*)&h;
}

// ============================================================================
// Prep 1 (merged): both projection GEMMs, fp16 output.
//   blockIdx.x <  32 : a_proj tile rows (2048 rows)
//   blockIdx.x >= 32 : b_proj tile rows (512 rows, + b1)
// 64x64 tile, BK=16, 128 threads, 8x4 microtile. 320 CTAs -> ~2 CTAs/SM.
// ============================================================================
__global__ __launch_bounds__(128) void proj_both_kernel(
    const float* __restrict__ PhiA, const float* __restrict__ PhiB,
    const float* __restrict__ W1a, const float* __restrict__ W1b,
    const float* __restrict__ b1,
    __half* __restrict__ aout, __half* __restrict__ bout)
{
    __shared__ float As[16][68];
    __shared__ float Bs[16][68];
    const int bx = blockIdx.x;
    const bool isB = bx >= 32;
    const float* X = isB ? PhiB : PhiA;
    const float* W = isB ? W1b : W1a;
    const float* bias = isB ? b1 : nullptr;
    __half* out = isB ? bout : aout;
    const int r0 = (isB ? bx - 32 : bx) * 64;
    const int c0 = blockIdx.y * 64;

    const int tid = threadIdx.x;
    const int tx = tid & 15;   // col group of 4
    const int ty = tid >> 4;   // row group of 8
    float acc[8][4] = {};

    for (int k0 = 0; k0 < D_DIM; k0 += 16) {
        #pragma unroll
        for (int i = 0; i < 8; i++) {
            int idx = tid + i * 128;
            int m = idx >> 4, k = idx & 15;
            As[k][m] = X[(size_t)(r0 + m) * D_DIM + k0 + k];
        }
        #pragma unroll
        for (int i = 0; i < 8; i++) {
            int idx = tid + i * 128;
            int k = idx >> 6, c = idx & 63;
            Bs[k][c] = W[(size_t)(k0 + k) * H1_DIM + c0 + c];
        }
        __syncthreads();
        #pragma unroll
        for (int kk = 0; kk < 16; kk++) {
            float a[8], b[4];
            *(float4*)&a[0] = *(const float4*)&As[kk][ty * 8];
            *(float4*)&a[4] = *(const float4*)&As[kk][ty * 8 + 4];
            *(float4*)&b[0] = *(const float4*)&Bs[kk][tx * 4];
            #pragma unroll
            for (int i = 0; i < 8; i++)
                #pragma unroll
                for (int j = 0; j < 4; j++) acc[i][j] += a[i] * b[j];
        }
        __syncthreads();
    }
    #pragma unroll
    for (int i = 0; i < 8; i++) {
        const int r = r0 + ty * 8 + i, c = c0 + tx * 4;
        float v0 = acc[i][0], v1 = acc[i][1], v2 = acc[i][2], v3 = acc[i][3];
        if (bias) { v0 += bias[c]; v1 += bias[c + 1]; v2 += bias[c + 2]; v3 += bias[c + 3]; }
        __half2 h01 = __floats2half2_rn(v0, v1);
        __half2 h23 = __floats2half2_rn(v2, v3);
        uint2 u;
        u.x = *(uint32_t*)&h01;
        u.y = *(uint32_t*)&h23;
        *(uint2*)&out[(size_t)r * H1_DIM + c] = u;
    }
}

// ============================================================================
// Prep 2: W2 (512x256 fp32, [k][j]) -> pre-fragmented fp16 mma-B layout.
// w2frag[(kb*16 + jbp)*32 + lane] = uint4 {b0,b1 (j=jbp*16+g), b0,b1 (j+8)}
// ============================================================================
__global__ void w2frag_kernel(const float* __restrict__ W2, uint4* __restrict__ out) {
    const int kb = blockIdx.x;     // 0..31
    const int jbp = blockIdx.y;    // 0..15
    const int lid = threadIdx.x;   // 0..31
    const int gg = lid >> 2, tg = lid & 3;
    const int k0 = kb * 16 + 2 * tg;
    const int j0 = jbp * 16 + gg;

    auto p2 = [&](int k, int j) {
        __half2 h = __floats2half2_rn(W2[(size_t)k * H2_DIM + j],
                                      W2[(size_t)(k + 1) * H2_DIM + j]);
        return *(uint32_t*)&h;
    };
    uint4 u;
    u.x = p2(k0, j0);
    u.y = p2(k0 + 8, j0);
    u.z = p2(k0, j0 + 8);
    u.w = p2(k0 + 8, j0 + 8);
    out[(kb * 16 + jbp) * 32 + lid] = u;
}

// ============================================================================
// Main fused kernel
//   CTA: 1 n x 64 m x 256 h2. 128 threads, 4 warps = 2 m-bands x 2 j-bands,
//   warp tile 32m x 128j. K=512 in 8 stages of 64. 2 CTAs/SM resident ->
//   prolog/epilog/barrier dead time of one CTA overlaps the other's MMAs.
//   B: LDG.128 of pre-fragmented W2, double-buffered in registers.
//   A: bproj fp16 cp.async-staged; fragments = HADD2+HMAX2 in registers.
//   Epilogue: relu(+b2) dot w3 in registers, shfl + smem reduce, one store.
// ============================================================================
__global__ __launch_bounds__(128, 2) void pair_mlp_main(
    const __half* __restrict__ aprojh, const __half* __restrict__ bprojh,
    const uint4* __restrict__ w2f, const float* __restrict__ b2,
    const float* __restrict__ w3, const float* __restrict__ b3,
    float* __restrict__ out)
{
    __shared__ __align__(8) __half s_arowh[H1_DIM];
    __shared__ float s_b2[H2_DIM];
    __shared__ float s_w3[H2_DIM];
    __shared__ float s_part[64 * 2];
    __shared__ __align__(16) __half s_bp[2][64][72];   // 64 data halves + pad

    const int tid = threadIdx.x;
    const int wid = tid >> 5;
    const int lid = tid & 31;
    const int wr  = wid >> 1;   // m band: rows wr*32 (0..1)
    const int wc  = wid & 1;    // j band: cols wc*128
    const int g   = lid >> 2;
    const int tg  = lid & 3;

    const int t  = blockIdx.x;            // 0..8191
    const int b  = t >> 12;
    const int n  = (t >> 2) & (N_DIM - 1);
    const int m0 = (t & 3) * 64;

    // arow: 512 halves = 128 x uint2
    ((uint2*)s_arowh)[tid] =
        ((const uint2*)(aprojh + (size_t)(b * N_DIM + n) * H1_DIM))[tid];
    s_b2[tid] = b2[tid];         s_b2[tid + 128] = b2[tid + 128];
    s_w3[tid] = w3[tid];         s_w3[tid + 128] = w3[tid + 128];

    const __half* bpg = bprojh + (size_t)(b * M_DIM + m0) * H1_DIM;

    // cp.async: stage s of bproj fp16 (64 rows x 64 halves) into s_bp[s&1]
    auto issue_bp = [&](int s) {
        const int buf = s & 1;
        const int kc = s * 64;
        #pragma unroll
        for (int i = 0; i < 4; i++) {
            int idx = tid + i * 128;          // 0..511
            int row = idx >> 3, c = idx & 7;  // 8 x 16B per row
            cp16(smem_to_u32(&s_bp[buf][row][c * 8]),
                 bpg + (size_t)row * H1_DIM + kc + c * 8);
        }
        cp_commit();
    };
    issue_bp(0);

    float acc[2][16][4];
    #pragma unroll
    for (int mt = 0; mt < 2; mt++)
        #pragma unroll
        for (int nt = 0; nt < 16; nt++)
            #pragma unroll
            for (int q = 0; q < 4; q++) acc[mt][nt][q] = 0.0f;

    const int r0 = wr * 32 + g;   // warp rows: r0, r0+8, r0+16, r0+24

    // B-fragment register double buffer, prefetched by global k16-slice kb
    uint4 bfa[8], bfb[8];
    auto ldB = [&](uint4* dst, int kb) {
        const int fb = (kb * 16 + wc * 8) * 32 + lid;
        #pragma unroll
        for (int p = 0; p < 8; p++) dst[p] = w2f[fb + p * 32];
    };
    ldB(bfa, 0);

    for (int s = 0; s < 8; s++) {
        const int buf = s & 1;
        const int kc = s * 64;
        __syncthreads();                           // close reads of s_bp[buf^1]
        if (s + 1 < 8) {
            issue_bp(s + 1);
            asm volatile("cp.async.wait_group 1;" ::: "memory");
        } else {
            asm volatile("cp.async.wait_group 0;" ::: "memory");
        }
        __syncthreads();                           // stage-s data visible

        #pragma unroll
        for (int kk = 0; kk < 4; kk++) {
            const int kb = s * 4 + kk;
            uint4* cur = (kb & 1) ? bfb : bfa;
            uint4* nxt = (kb & 1) ? bfa : bfb;
            if (kb < 31) ldB(nxt, kb + 1);         // prefetch next slice

            // ---- A fragments: fp16 relu(arow + bp), 2 ops each ----
            const int k0 = kk * 16 + 2 * tg;
            const __half2 a0h = *(const __half2*)&s_arowh[kc + k0];
            const __half2 a8h = *(const __half2*)&s_arowh[kc + k0 + 8];
            uint32_t a0[4], a1[4];
            a0[0] = fragAB(a0h, *(const __half2*)&s_bp[buf][r0     ][k0]);
            a0[1] = fragAB(a0h, *(const __half2*)&s_bp[buf][r0 +  8][k0]);
            a0[2] = fragAB(a8h, *(const __half2*)&s_bp[buf][r0     ][k0 + 8]);
            a0[3] = fragAB(a8h, *(const __half2*)&s_bp[buf][r0 +  8][k0 + 8]);
            a1[0] = fragAB(a0h, *(const __half2*)&s_bp[buf][r0 + 16][k0]);
            a1[1] = fragAB(a0h, *(const __half2*)&s_bp[buf][r0 + 24][k0]);
            a1[2] = fragAB(a8h, *(const __half2*)&s_bp[buf][r0 + 16][k0 + 8]);
            a1[3] = fragAB(a8h, *(const __half2*)&s_bp[buf][r0 + 24][k0 + 8]);

            // ---- 32 MMAs on the current B slice ----
            #pragma unroll
            for (int p = 0; p < 8; p++) {
                mma_f16(acc[0][2 * p + 0], a0, cur[p].x, cur[p].y);
                mma_f16(acc[0][2 * p + 1], a0, cur[p].z, cur[p].w);
                mma_f16(acc[1][2 * p + 0], a1, cur[p].x, cur[p].y);
                mma_f16(acc[1][2 * p + 1], a1, cur[p].z, cur[p].w);
            }
        }
    }

    // ---- epilogue: out[row] = sum_j relu(D[row,j]+b2[j])*w3[j] + b3 ----
    float p0 = 0.0f, p1 = 0.0f, p2s = 0.0f, p3s = 0.0f;  // rows r0,+8,+16,+24
    #pragma unroll
    for (int nt = 0; nt < 16; nt++) {
        const int j = wc * 128 + nt * 8 + 2 * tg;
        const float b2a = s_b2[j], b2b = s_b2[j + 1];
        const float w3a = s_w3[j], w3b = s_w3[j + 1];
        const float* c0 = acc[0][nt];
        const float* c1 = acc[1][nt];
        p0  += fmaxf(c0[0] + b2a, 0.0f) * w3a + fmaxf(c0[1] + b2b, 0.0f) * w3b;
        p1  += fmaxf(c0[2] + b2a, 0.0f) * w3a + fmaxf(c0[3] + b2b, 0.0f) * w3b;
        p2s += fmaxf(c1[0] + b2a, 0.0f) * w3a + fmaxf(c1[1] + b2b, 0.0f) * w3b;
        p3s += fmaxf(c1[2] + b2a, 0.0f) * w3a + fmaxf(c1[3] + b2b, 0.0f) * w3b;
    }
    #pragma unroll
    for (int off = 1; off < 4; off <<= 1) {
        p0  += __shfl_xor_sync(0xffffffffu, p0, off);
        p1  += __shfl_xor_sync(0xffffffffu, p1, off);
        p2s += __shfl_xor_sync(0xffffffffu, p2s, off);
        p3s += __shfl_xor_sync(0xffffffffu, p3s, off);
    }

    __syncthreads();
    if (tg == 0) {
        s_part[(r0     ) * 2 + wc] = p0;
        s_part[(r0 +  8) * 2 + wc] = p1;
        s_part[(r0 + 16) * 2 + wc] = p2s;
        s_part[(r0 + 24) * 2 + wc] = p3s;
    }
    __syncthreads();
    if (tid < 64) {
        float v = s_part[tid * 2 + 0] + s_part[tid * 2 + 1] + b3[0];
        out[(size_t)(b * N_DIM + n) * M_DIM + m0 + tid] = v;
    }
}

// ============================================================================
// Launch
// ============================================================================
extern "C" void kernel_launch(void* const* d_in, const int* in_sizes, int n_in,
                              void* d_out, int out_size) {
    const float* PhiA = (const float*)d_in[0];
    const float* PhiB = (const float*)d_in[1];
    const float* W1a  = (const float*)d_in[2];
    const float* W1b  = (const float*)d_in[3];
    const float* b1   = (const float*)d_in[4];
    const float* W2   = (const float*)d_in[5];
    const float* b2   = (const float*)d_in[6];
    const float* W3   = (const float*)d_in[7];
    const float* b3   = (const float*)d_in[8];
    float* out = (float*)d_out;

    __half* aprojh = nullptr;
    __half* bprojh = nullptr;
    uint4* w2f = nullptr;
    cudaGetSymbolAddress((void**)&aprojh, g_aprojh);
    cudaGetSymbolAddress((void**)&bprojh, g_bprojh);
    cudaGetSymbolAddress((void**)&w2f, g_w2frag);

    // both projections in one launch (A: 32 row-tiles, B: 8 row-tiles)
    proj_both_kernel<<<dim3(40, H1_DIM / 64), 128>>>(
        PhiA, PhiB, W1a, W1b, b1, aprojh, bprojh);
    // W2 -> pre-fragmented fp16 B-operand layout
    w2frag_kernel<<<dim3(32, 16), 32>>>(W2, w2f);

    pair_mlp_main<<<B_DIM * N_DIM * (M_DIM / 64), 128>>>(
        aprojh, bprojh, w2f, b2, W3, b3, out);
}

// round 9
// speedup vs baseline: 1.7236x; 1.0130x over previous
#include <cuda_runtime.h>
#include <cuda_fp16.h>
#include <cstdint>

// ============================================================================
// Problem constants
// ============================================================================
#define B_DIM  2
#define N_DIM  1024
#define M_DIM  256
#define D_DIM  576
#define H1_DIM 512
#define H2_DIM 256

// Scratch (allocation-free rule: __device__ globals)
// aprojh / bprojh are stored K-PERMUTED: within each 16-column block, the
// half2 pair for logical k-pair p (pairs 0..7) lives at slot_pair
// (p&3)*2 + (p>>2). This makes each mma-lane's two half2s (k0,k0+1) and
// (k0+8,k0+9) adjacent -> one LDS.64 in the main kernel.
__device__ __half g_aprojh[B_DIM * N_DIM * H1_DIM];   // fp16(a_proj), k-permuted
__device__ __half g_bprojh[B_DIM * M_DIM * H1_DIM];   // fp16(b_proj + b1), k-permuted
__device__ uint4  g_w2frag[32 * 16 * 32];             // W2 pre-packed mma B-fragments

// storage half-index of the pair starting at even logical column c
__host__ __device__ __forceinline__ int permslot(int c) {
    int p = (c & 15) >> 1;
    return (c & ~15) + (((p & 3) * 2 + (p >> 2)) << 1);
}

// ============================================================================
// PTX helpers (base ISA — harness compiles for compute_103, no 'a' features)
// ============================================================================
__device__ __forceinline__ uint32_t smem_to_u32(const void* p) {
    uint32_t a;
    asm("{ .reg .u64 t; cvta.to.shared.u64 t, %1; cvt.u32.u64 %0, t; }" : "=r"(a) : "l"(p));
    return a;
}

__device__ __forceinline__ void cp16(uint32_t s, const void* g) {
    asm volatile("cp.async.cg.shared.global [%0], [%1], 16;" :: "r"(s), "l"(g) : "memory");
}
__device__ __forceinline__ void cp_commit() {
    asm volatile("cp.async.commit_group;" ::: "memory");
}

__device__ __forceinline__ void mma_f16(float* c, const uint32_t* a, uint32_t b0, uint32_t b1) {
    asm volatile(
        "mma.sync.aligned.m16n8k16.row.col.f32.f16.f16.f32 "
        "{%0,%1,%2,%3}, {%4,%5,%6,%7}, {%8,%9}, {%0,%1,%2,%3};"
        : "+f"(c[0]), "+f"(c[1]), "+f"(c[2]), "+f"(c[3])
        : "r"(a[0]), "r"(a[1]), "r"(a[2]), "r"(a[3]), "r"(b0), "r"(b1));
}

// h1 fragment: fp16 relu(a + b), 2 ops (HADD2 + HMAX2)
__device__ __forceinline__ uint32_t fragAB(uint32_t a, uint32_t b) {
    __half2 z = __float2half2_rn(0.0f);
    __half2 h = __hmax2(__hadd2(*(__half2*)&a, *(__half2*)&b), z);
    return *(uint32_t*)&h;
}

// ============================================================================
// Prep 1 (merged): both projection GEMMs, fp16 k-permuted output.
//   blockIdx.x <  32 : a_proj tile rows (2048 rows)
//   blockIdx.x >= 32 : b_proj tile rows (512 rows, + b1)
// 64x32 tile, BK=16, 64 threads, 8x4 microtile. 640 CTAs -> ~4.3 CTAs/SM.
// ============================================================================
__global__ __launch_bounds__(64) void proj_both_kernel(
    const float* __restrict__ PhiA, const float* __restrict__ PhiB,
    const float* __restrict__ W1a, const float* __restrict__ W1b,
    const float* __restrict__ b1,
    __half* __restrict__ aout, __half* __restrict__ bout)
{
    __shared__ float As[16][68];
    __shared__ float Bs[16][36];
    const int bx = blockIdx.x;
    const bool isB = bx >= 32;
    const float* X = isB ? PhiB : PhiA;
    const float* W = isB ? W1b : W1a;
    const float* bias = isB ? b1 : nullptr;
    __half* out = isB ? bout : aout;
    const int r0 = (isB ? bx - 32 : bx) * 64;
    const int c0 = blockIdx.y * 32;

    const int tid = threadIdx.x;   // 0..63
    const int tx = tid & 7;        // col group of 4
    const int ty = tid >> 3;       // row group of 8
    float acc[8][4] = {};

    for (int k0 = 0; k0 < D_DIM; k0 += 16) {
        #pragma unroll
        for (int i = 0; i < 16; i++) {
            int idx = tid + i * 64;
            int m = idx >> 4, k = idx & 15;
            As[k][m] = X[(size_t)(r0 + m) * D_DIM + k0 + k];
        }
        #pragma unroll
        for (int i = 0; i < 8; i++) {
            int idx = tid + i * 64;
            int k = idx >> 5, c = idx & 31;
            Bs[k][c] = W[(size_t)(k0 + k) * H1_DIM + c0 + c];
        }
        __syncthreads();
        #pragma unroll
        for (int kk = 0; kk < 16; kk++) {
            float a[8], b[4];
            *(float4*)&a[0] = *(const float4*)&As[kk][ty * 8];
            *(float4*)&a[4] = *(const float4*)&As[kk][ty * 8 + 4];
            *(float4*)&b[0] = *(const float4*)&Bs[kk][tx * 4];
            #pragma unroll
            for (int i = 0; i < 8; i++)
                #pragma unroll
                for (int j = 0; j < 4; j++) acc[i][j] += a[i] * b[j];
        }
        __syncthreads();
    }
    const int c = c0 + tx * 4;              // even, c%4==0
    const int s0 = permslot(c);             // pair (c, c+1)
    const int s1 = permslot(c + 2);         // pair (c+2, c+3)
    #pragma unroll
    for (int i = 0; i < 8; i++) {
        const int r = r0 + ty * 8 + i;
        float v0 = acc[i][0], v1 = acc[i][1], v2 = acc[i][2], v3 = acc[i][3];
        if (bias) { v0 += bias[c]; v1 += bias[c + 1]; v2 += bias[c + 2]; v3 += bias[c + 3]; }
        __half2 h01 = __floats2half2_rn(v0, v1);
        __half2 h23 = __floats2half2_rn(v2, v3);
        *(__half2*)&out[(size_t)r * H1_DIM + s0] = h01;
        *(__half2*)&out[(size_t)r * H1_DIM + s1] = h23;
    }
}

// ============================================================================
// Prep 2: W2 (512x256 fp32, [k][j]) -> pre-fragmented fp16 mma-B layout.
// w2frag[(kb*16 + jbp)*32 + lane] = uint4 {b0,b1 (j=jbp*16+g), b0,b1 (j+8)}
// ============================================================================
__global__ void w2frag_kernel(const float* __restrict__ W2, uint4* __restrict__ out) {
    const int kb = blockIdx.x;     // 0..31
    const int jbp = blockIdx.y;    // 0..15
    const int lid = threadIdx.x;   // 0..31
    const int gg = lid >> 2, tg = lid & 3;
    const int k0 = kb * 16 + 2 * tg;
    const int j0 = jbp * 16 + gg;

    auto p2 = [&](int k, int j) {
        __half2 h = __floats2half2_rn(W2[(size_t)k * H2_DIM + j],
                                      W2[(size_t)(k + 1) * H2_DIM + j]);
        return *(uint32_t*)&h;
    };
    uint4 u;
    u.x = p2(k0, j0);
    u.y = p2(k0 + 8, j0);
    u.z = p2(k0, j0 + 8);
    u.w = p2(k0 + 8, j0 + 8);
    out[(kb * 16 + jbp) * 32 + lid] = u;
}

// ============================================================================
// Main fused kernel
//   CTA: 1 n x 64 m x 256 h2. 128 threads, 4 warps = 2 m-bands x 2 j-bands,
//   warp tile 32m x 128j. K=512 in 8 stages of 64. 2 CTAs/SM resident.
//   B: LDG.128 of pre-fragmented W2, double-buffered in registers.
//   A: bproj fp16 cp.async-staged (k-permuted, stride-80 rows -> each lane's
//      two half2s are one conflict-free LDS.64); frags = HADD2+HMAX2.
//   Epilogue: relu(+b2) dot w3 in registers, shfl + smem reduce, one store.
// ============================================================================
__global__ __launch_bounds__(128, 2) void pair_mlp_main(
    const __half* __restrict__ aprojh, const __half* __restrict__ bprojh,
    const uint4* __restrict__ w2f, const float* __restrict__ b2,
    const float* __restrict__ w3, const float* __restrict__ b3,
    float* __restrict__ out)
{
    __shared__ __align__(16) __half s_arowh[H1_DIM];
    __shared__ float s_b2[H2_DIM];
    __shared__ float s_w3[H2_DIM];
    __shared__ float s_part[64 * 2];
    __shared__ __align__(16) __half s_bp[2][64][80];   // 64 data halves + pad->40 words

    const int tid = threadIdx.x;
    const int wid = tid >> 5;
    const int lid = tid & 31;
    const int wr  = wid >> 1;   // m band: rows wr*32 (0..1)
    const int wc  = wid & 1;    // j band: cols wc*128
    const int g   = lid >> 2;
    const int tg  = lid & 3;

    const int t  = blockIdx.x;            // 0..8191
    const int b  = t >> 12;
    const int n  = (t >> 2) & (N_DIM - 1);
    const int m0 = (t & 3) * 64;

    // arow: 512 halves = 128 x uint2 (already k-permuted in GMEM)
    ((uint2*)s_arowh)[tid] =
        ((const uint2*)(aprojh + (size_t)(b * N_DIM + n) * H1_DIM))[tid];
    s_b2[tid] = b2[tid];         s_b2[tid + 128] = b2[tid + 128];
    s_w3[tid] = w3[tid];         s_w3[tid + 128] = w3[tid + 128];

    const __half* bpg = bprojh + (size_t)(b * M_DIM + m0) * H1_DIM;

    // cp.async: stage s of bproj fp16 (64 rows x 64 halves) into s_bp[s&1]
    auto issue_bp = [&](int s) {
        const int buf = s & 1;
        const int kc = s * 64;
        #pragma unroll
        for (int i = 0; i < 4; i++) {
            int idx = tid + i * 128;          // 0..511
            int row = idx >> 3, c = idx & 7;  // 8 x 16B per row
            cp16(smem_to_u32(&s_bp[buf][row][c * 8]),
                 bpg + (size_t)row * H1_DIM + kc + c * 8);
        }
        cp_commit();
    };
    issue_bp(0);

    float acc[2][16][4];
    #pragma unroll
    for (int mt = 0; mt < 2; mt++)
        #pragma unroll
        for (int nt = 0; nt < 16; nt++)
            #pragma unroll
            for (int q = 0; q < 4; q++) acc[mt][nt][q] = 0.0f;

    const int r0 = wr * 32 + g;   // warp rows: r0, r0+8, r0+16, r0+24

    // B-fragment register double buffer, prefetched by global k16-slice kb
    uint4 bfa[8], bfb[8];
    auto ldB = [&](uint4* dst, int kb) {
        const int fb = (kb * 16 + wc * 8) * 32 + lid;
        #pragma unroll
        for (int p = 0; p < 8; p++) dst[p] = w2f[fb + p * 32];
    };
    ldB(bfa, 0);

    for (int s = 0; s < 8; s++) {
        const int buf = s & 1;
        const int kc = s * 64;
        __syncthreads();                           // close reads of s_bp[buf^1]
        if (s + 1 < 8) {
            issue_bp(s + 1);
            asm volatile("cp.async.wait_group 1;" ::: "memory");
        } else {
            asm volatile("cp.async.wait_group 0;" ::: "memory");
        }
        __syncthreads();                           // stage-s cp.async data visible

        #pragma unroll
        for (int kk = 0; kk < 4; kk++) {
            const int kb = s * 4 + kk;
            uint4* cur = (kb & 1) ? bfb : bfa;
            uint4* nxt = (kb & 1) ? bfa : bfb;
            if (kb < 31) ldB(nxt, kb + 1);         // prefetch next slice

            // ---- A fragments (k-permuted layout): one LDS.64 per source ----
            const int ko = kk * 16 + tg * 4;       // {a(k0,k0+1), a(k0+8,k0+9)}
            const uint2 ua = *(const uint2*)&s_arowh[kc + ko];
            const uint2 u0 = *(const uint2*)&s_bp[buf][r0     ][ko];
            const uint2 u1 = *(const uint2*)&s_bp[buf][r0 +  8][ko];
            const uint2 u2 = *(const uint2*)&s_bp[buf][r0 + 16][ko];
            const uint2 u3 = *(const uint2*)&s_bp[buf][r0 + 24][ko];
            uint32_t a0[4], a1[4];
            a0[0] = fragAB(ua.x, u0.x);
            a0[1] = fragAB(ua.x, u1.x);
            a0[2] = fragAB(ua.y, u0.y);
            a0[3] = fragAB(ua.y, u1.y);
            a1[0] = fragAB(ua.x, u2.x);
            a1[1] = fragAB(ua.x, u3.x);
            a1[2] = fragAB(ua.y, u2.y);
            a1[3] = fragAB(ua.y, u3.y);

            // ---- 32 MMAs on the current B slice ----
            #pragma unroll
            for (int p = 0; p < 8; p++) {
                mma_f16(acc[0][2 * p + 0], a0, cur[p].x, cur[p].y);
                mma_f16(acc[0][2 * p + 1], a0, cur[p].z, cur[p].w);
                mma_f16(acc[1][2 * p + 0], a1, cur[p].x, cur[p].y);
                mma_f16(acc[1][2 * p + 1], a1, cur[p].z, cur[p].w);
            }
        }
    }

    // ---- epilogue: out[row] = sum_j relu(D[row,j]+b2[j])*w3[j] + b3 ----
    float p0 = 0.0f, p1 = 0.0f, p2s = 0.0f, p3s = 0.0f;  // rows r0,+8,+16,+24
    #pragma unroll
    for (int nt = 0; nt < 16; nt++) {
        const int j = wc * 128 + nt * 8 + 2 * tg;
        const float b2a = s_b2[j], b2b = s_b2[j + 1];
        const float w3a = s_w3[j], w3b = s_w3[j + 1];
        const float* c0 = acc[0][nt];
        const float* c1 = acc[1][nt];
        p0  += fmaxf(c0[0] + b2a, 0.0f) * w3a + fmaxf(c0[1] + b2b, 0.0f) * w3b;
        p1  += fmaxf(c0[2] + b2a, 0.0f) * w3a + fmaxf(c0[3] + b2b, 0.0f) * w3b;
        p2s += fmaxf(c1[0] + b2a, 0.0f) * w3a + fmaxf(c1[1] + b2b, 0.0f) * w3b;
        p3s += fmaxf(c1[2] + b2a, 0.0f) * w3a + fmaxf(c1[3] + b2b, 0.0f) * w3b;
    }
    #pragma unroll
    for (int off = 1; off < 4; off <<= 1) {
        p0  += __shfl_xor_sync(0xffffffffu, p0, off);
        p1  += __shfl_xor_sync(0xffffffffu, p1, off);
        p2s += __shfl_xor_sync(0xffffffffu, p2s, off);
        p3s += __shfl_xor_sync(0xffffffffu, p3s, off);
    }

    __syncthreads();
    if (tg == 0) {
        s_part[(r0     ) * 2 + wc] = p0;
        s_part[(r0 +  8) * 2 + wc] = p1;
        s_part[(r0 + 16) * 2 + wc] = p2s;
        s_part[(r0 + 24) * 2 + wc] = p3s;
    }
    __syncthreads();
    if (tid < 64) {
        float v = s_part[tid * 2 + 0] + s_part[tid * 2 + 1] + b3[0];
        out[(size_t)(b * N_DIM + n) * M_DIM + m0 + tid] = v;
    }
}

// ============================================================================
// Launch
// ============================================================================
extern "C" void kernel_launch(void* const* d_in, const int* in_sizes, int n_in,
                              void* d_out, int out_size) {
    const float* PhiA = (const float*)d_in[0];
    const float* PhiB = (const float*)d_in[1];
    const float* W1a  = (const float*)d_in[2];
    const float* W1b  = (const float*)d_in[3];
    const float* b1   = (const float*)d_in[4];
    const float* W2   = (const float*)d_in[5];
    const float* b2   = (const float*)d_in[6];
    const float* W3   = (const float*)d_in[7];
    const float* b3   = (const float*)d_in[8];
    float* out = (float*)d_out;

    __half* aprojh = nullptr;
    __half* bprojh = nullptr;
    uint4* w2f = nullptr;
    cudaGetSymbolAddress((void**)&aprojh, g_aprojh);
    cudaGetSymbolAddress((void**)&bprojh, g_bprojh);
    cudaGetSymbolAddress((void**)&w2f, g_w2frag);

    // both projections in one launch (A: 32 row-tiles, B: 8 row-tiles)
    proj_both_kernel<<<dim3(40, H1_DIM / 32), 64>>>(
        PhiA, PhiB, W1a, W1b, b1, aprojh, bprojh);
    // W2 -> pre-fragmented fp16 B-operand layout
    w2frag_kernel<<<dim3(32, 16), 32>>>(W2, w2f);

    pair_mlp_main<<<B_DIM * N_DIM * (M_DIM / 64), 128>>>(
        aprojh, bprojh, w2f, b2, W3, b3, out);
}

// round 10
// speedup vs baseline: 1.9422x; 1.1269x over previous
#include <cuda_runtime.h>
#include <cuda_fp16.h>
#include <cstdint>

// ============================================================================
// Problem constants
// ============================================================================
#define B_DIM  2
#define N_DIM  1024
#define M_DIM  256
#define D_DIM  576
#define H1_DIM 512
#define H2_DIM 256

// Scratch (allocation-free rule: __device__ globals)
// aprojh / bprojh are stored K-PERMUTED: within each 16-column block, the
// half2 pair for logical k-pair p (pairs 0..7) lives at slot (p&3)*2+(p>>2).
// Each mma-lane's two half2s (k0,k0+1),(k0+8,k0+9) are then one LDS.64.
__device__ __half g_aprojh[B_DIM * N_DIM * H1_DIM];   // fp16(a_proj), k-permuted
__device__ __half g_bprojh[B_DIM * M_DIM * H1_DIM];   // fp16(b_proj + b1), k-permuted
__device__ uint4  g_w2frag[32 * 16 * 32];             // W2  pre-packed mma B-fragments
__device__ uint4  g_w1afrag[36 * 32 * 32];            // W1a pre-packed mma B-fragments
__device__ uint4  g_w1bfrag[36 * 32 * 32];            // W1b pre-packed mma B-fragments

// storage half-index of the pair starting at even logical column c
__host__ __device__ __forceinline__ int permslot(int c) {
    int p = (c & 15) >> 1;
    return (c & ~15) + (((p & 3) * 2 + (p >> 2)) << 1);
}

// ============================================================================
// PTX helpers (base ISA — harness compiles for compute_103, no 'a' features)
// ============================================================================
__device__ __forceinline__ uint32_t smem_to_u32(const void* p) {
    uint32_t a;
    asm("{ .reg .u64 t; cvta.to.shared.u64 t, %1; cvt.u32.u64 %0, t; }" : "=r"(a) : "l"(p));
    return a;
}

__device__ __forceinline__ void cp16(uint32_t s, const void* g) {
    asm volatile("cp.async.cg.shared.global [%0], [%1], 16;" :: "r"(s), "l"(g) : "memory");
}
__device__ __forceinline__ void cp_commit() {
    asm volatile("cp.async.commit_group;" ::: "memory");
}

__device__ __forceinline__ void mma_f16(float* c, const uint32_t* a, uint32_t b0, uint32_t b1) {
    asm volatile(
        "mma.sync.aligned.m16n8k16.row.col.f32.f16.f16.f32 "
        "{%0,%1,%2,%3}, {%4,%5,%6,%7}, {%8,%9}, {%0,%1,%2,%3};"
        : "+f"(c[0]), "+f"(c[1]), "+f"(c[2]), "+f"(c[3])
        : "r"(a[0]), "r"(a[1]), "r"(a[2]), "r"(a[3]), "r"(b0), "r"(b1));
}

// h1 fragment: fp16 relu(a + b), 2 ops (HADD2 + HMAX2)
__device__ __forceinline__ uint32_t fragAB(uint32_t a, uint32_t b) {
    __half2 z = __float2half2_rn(0.0f);
    __half2 h = __hmax2(__hadd2(*(__half2*)&a, *(__half2*)&b), z);
    return *(uint32_t*)&h;
}

__device__ __forceinline__ uint32_t packh2(float2 v) {
    __half2 h = __floats2half2_rn(v.x, v.y);
    return *(uint32_t*)&h;
}

// ============================================================================
// Prep A: fragment ALL weight matrices into mma B-operand layout (fp16).
//   z=0: W2  [512][256] -> w2f  (kb<32, jbp<16)
//   z=1: W1a [576][512] -> w1af (kb<36, jbp<32)
//   z=2: W1b [576][512] -> w1bf
// frag[(kb*JBP + jbp)*32 + lane] = {b0,b1 (j=jbp*16+g), b0,b1 (j+8)}
// ============================================================================
__global__ void wfrag_kernel(
    const float* __restrict__ W2, const float* __restrict__ W1a,
    const float* __restrict__ W1b,
    uint4* __restrict__ w2f, uint4* __restrict__ w1af, uint4* __restrict__ w1bf)
{
    const int kb = blockIdx.x, jbp = blockIdx.y, z = blockIdx.z;
    const int lid = threadIdx.x;
    const float* W;
    uint4* out;
    int stride, outidx;
    if (z == 0) {
        if (kb >= 32 || jbp >= 16) return;
        W = W2; out = w2f; stride = H2_DIM;
        outidx = (kb * 16 + jbp) * 32 + lid;
    } else {
        W = (z == 1) ? W1a : W1b;
        out = (z == 1) ? w1af : w1bf;
        stride = H1_DIM;
        outidx = (kb * 32 + jbp) * 32 + lid;
    }
    const int gg = lid >> 2, tg = lid & 3;
    const int k0 = kb * 16 + 2 * tg;
    const int j0 = jbp * 16 + gg;

    auto p2 = [&](int k, int j) {
        __half2 h = __floats2half2_rn(W[(size_t)k * stride + j],
                                      W[(size_t)(k + 1) * stride + j]);
        return *(uint32_t*)&h;
    };
    uint4 u;
    u.x = p2(k0, j0);
    u.y = p2(k0 + 8, j0);
    u.z = p2(k0, j0 + 8);
    u.w = p2(k0 + 8, j0 + 8);
    out[outidx] = u;
}

// ============================================================================
// Prep B: projection GEMMs on tensor cores.
//   Rows 0..2047 -> a_proj = PhiA @ W1a       (output k-permuted fp16)
//   Rows 2048..2559 -> b_proj = PhiB @ W1b + b1
// CTA: 32 rows x 128 j. 128 threads, 4 warps (one 32j band each).
// K=576 in 36 k16-slices; A (Phi float2) + B (fragments) both register
// double-buffered, no smem. Grid 80 x 4 = 320 CTAs.
// ============================================================================
__global__ __launch_bounds__(128) void proj_mma_kernel(
    const float* __restrict__ PhiA, const float* __restrict__ PhiB,
    const float* __restrict__ b1,
    const uint4* __restrict__ w1af, const uint4* __restrict__ w1bf,
    __half* __restrict__ aprojh, __half* __restrict__ bprojh)
{
    const int tid = threadIdx.x;
    const int wid = tid >> 5, lid = tid & 31;
    const int g = lid >> 2, tg = lid & 3;
    const int m0 = blockIdx.x * 32;                 // global row base 0..2528
    const bool isB = m0 >= (B_DIM * N_DIM);
    const float* X = isB ? PhiB : PhiA;
    const int mloc = isB ? m0 - B_DIM * N_DIM : m0;
    const uint4* wf = isB ? w1bf : w1af;
    const int j0 = blockIdx.y * 128 + wid * 32;     // warp j band
    const int jbp0 = j0 >> 4;

    const float* Xr = X + (size_t)(mloc + g) * D_DIM;

    float acc[2][4][4] = {};

    uint4 bf0[2], bf1[2];
    auto ldB = [&](uint4* d, int kb) {
        const int fb = (kb * 32 + jbp0) * 32 + lid;
        d[0] = wf[fb];
        d[1] = wf[fb + 32];
    };
    float2 xc[8], xn[8];
    auto ldA = [&](float2* d, int kb) {
        const int k = kb * 16 + 2 * tg;
        d[0] = *(const float2*)(Xr + k);
        d[1] = *(const float2*)(Xr + 8 * D_DIM + k);
        d[2] = *(const float2*)(Xr + k + 8);
        d[3] = *(const float2*)(Xr + 8 * D_DIM + k + 8);
        d[4] = *(const float2*)(Xr + 16 * D_DIM + k);
        d[5] = *(const float2*)(Xr + 24 * D_DIM + k);
        d[6] = *(const float2*)(Xr + 16 * D_DIM + k + 8);
        d[7] = *(const float2*)(Xr + 24 * D_DIM + k + 8);
    };
    ldB(bf0, 0);
    ldA(xc, 0);

    #pragma unroll 4
    for (int kb = 0; kb < 36; kb++) {
        uint4* cur = (kb & 1) ? bf1 : bf0;
        uint4* nxt = (kb & 1) ? bf0 : bf1;
        float2* xcur = (kb & 1) ? xn : xc;
        float2* xnxt = (kb & 1) ? xc : xn;
        if (kb < 35) { ldB(nxt, kb + 1); ldA(xnxt, kb + 1); }

        uint32_t a0[4], a1[4];
        a0[0] = packh2(xcur[0]); a0[1] = packh2(xcur[1]);
        a0[2] = packh2(xcur[2]); a0[3] = packh2(xcur[3]);
        a1[0] = packh2(xcur[4]); a1[1] = packh2(xcur[5]);
        a1[2] = packh2(xcur[6]); a1[3] = packh2(xcur[7]);

        #pragma unroll
        for (int p = 0; p < 2; p++) {
            mma_f16(acc[0][2 * p + 0], a0, cur[p].x, cur[p].y);
            mma_f16(acc[0][2 * p + 1], a0, cur[p].z, cur[p].w);
            mma_f16(acc[1][2 * p + 0], a1, cur[p].x, cur[p].y);
            mma_f16(acc[1][2 * p + 1], a1, cur[p].z, cur[p].w);
        }
    }

    // epilogue: +b1 (B side), fp16, k-permuted scatter
    __half* outb = isB ? (bprojh + (size_t)mloc * H1_DIM)
                       : (aprojh + (size_t)m0 * H1_DIM);
    #pragma unroll
    for (int mt = 0; mt < 2; mt++) {
        __half* orow0 = outb + (size_t)(mt * 16 + g) * H1_DIM;
        __half* orow1 = orow0 + 8 * H1_DIM;
        #pragma unroll
        for (int nt = 0; nt < 4; nt++) {
            const int j = j0 + nt * 8 + 2 * tg;
            const int sl = permslot(j);
            float v0 = acc[mt][nt][0], v1 = acc[mt][nt][1];
            float v2 = acc[mt][nt][2], v3 = acc[mt][nt][3];
            if (isB) {
                const float ba = b1[j], bb = b1[j + 1];
                v0 += ba; v1 += bb; v2 += ba; v3 += bb;
            }
            *(__half2*)&orow0[sl] = __floats2half2_rn(v0, v1);
            *(__half2*)&orow1[sl] = __floats2half2_rn(v2, v3);
        }
    }
}

// ============================================================================
// Main fused kernel
//   CTA: 1 n x 64 m x 256 h2. 128 threads, 4 warps = 2 m-bands x 2 j-bands,
//   warp tile 32m x 128j. K=512 in 8 stages of 64. 2 CTAs/SM resident.
//   B: LDG.128 of pre-fragmented W2, double-buffered in registers.
//   A: bproj fp16 cp.async-staged (k-permuted, stride-80 rows); frags =
//      HADD2+HMAX2 from one LDS.64 per source.
//   Epilogue: relu(+b2) dot w3 in registers, shfl + smem reduce, one store.
// ============================================================================
__global__ __launch_bounds__(128, 2) void pair_mlp_main(
    const __half* __restrict__ aprojh, const __half* __restrict__ bprojh,
    const uint4* __restrict__ w2f, const float* __restrict__ b2,
    const float* __restrict__ w3, const float* __restrict__ b3,
    float* __restrict__ out)
{
    __shared__ __align__(16) __half s_arowh[H1_DIM];
    __shared__ float s_b2[H2_DIM];
    __shared__ float s_w3[H2_DIM];
    __shared__ float s_part[64 * 2];
    __shared__ __align__(16) __half s_bp[2][64][80];   // 64 data halves + pad

    const int tid = threadIdx.x;
    const int wid = tid >> 5;
    const int lid = tid & 31;
    const int wr  = wid >> 1;   // m band: rows wr*32 (0..1)
    const int wc  = wid & 1;    // j band: cols wc*128
    const int g   = lid >> 2;
    const int tg  = lid & 3;

    const int t  = blockIdx.x;            // 0..8191
    const int b  = t >> 12;
    const int n  = (t >> 2) & (N_DIM - 1);
    const int m0 = (t & 3) * 64;

    // arow: 512 halves = 128 x uint2 (k-permuted in GMEM)
    ((uint2*)s_arowh)[tid] =
        ((const uint2*)(aprojh + (size_t)(b * N_DIM + n) * H1_DIM))[tid];
    s_b2[tid] = b2[tid];         s_b2[tid + 128] = b2[tid + 128];
    s_w3[tid] = w3[tid];         s_w3[tid + 128] = w3[tid + 128];

    const __half* bpg = bprojh + (size_t)(b * M_DIM + m0) * H1_DIM;

    // cp.async: stage s of bproj fp16 (64 rows x 64 halves) into s_bp[s&1]
    auto issue_bp = [&](int s) {
        const int buf = s & 1;
        const int kc = s * 64;
        #pragma unroll
        for (int i = 0; i < 4; i++) {
            int idx = tid + i * 128;          // 0..511
            int row = idx >> 3, c = idx & 7;  // 8 x 16B per row
            cp16(smem_to_u32(&s_bp[buf][row][c * 8]),
                 bpg + (size_t)row * H1_DIM + kc + c * 8);
        }
        cp_commit();
    };
    issue_bp(0);

    float acc[2][16][4];
    #pragma unroll
    for (int mt = 0; mt < 2; mt++)
        #pragma unroll
        for (int nt = 0; nt < 16; nt++)
            #pragma unroll
            for (int q = 0; q < 4; q++) acc[mt][nt][q] = 0.0f;

    const int r0 = wr * 32 + g;   // warp rows: r0, r0+8, r0+16, r0+24

    // B-fragment register double buffer, prefetched by global k16-slice kb
    uint4 bfa[8], bfb[8];
    auto ldB = [&](uint4* dst, int kb) {
        const int fb = (kb * 16 + wc * 8) * 32 + lid;
        #pragma unroll
        for (int p = 0; p < 8; p++) dst[p] = w2f[fb + p * 32];
    };
    ldB(bfa, 0);

    for (int s = 0; s < 8; s++) {
        const int buf = s & 1;
        const int kc = s * 64;
        __syncthreads();                           // close reads of s_bp[buf^1]
        if (s + 1 < 8) {
            issue_bp(s + 1);
            asm volatile("cp.async.wait_group 1;" ::: "memory");
        } else {
            asm volatile("cp.async.wait_group 0;" ::: "memory");
        }
        __syncthreads();                           // stage-s cp.async data visible

        #pragma unroll
        for (int kk = 0; kk < 4; kk++) {
            const int kb = s * 4 + kk;
            uint4* cur = (kb & 1) ? bfb : bfa;
            uint4* nxt = (kb & 1) ? bfa : bfb;
            if (kb < 31) ldB(nxt, kb + 1);         // prefetch next slice

            // ---- A fragments (k-permuted layout): one LDS.64 per source ----
            const int ko = kk * 16 + tg * 4;       // {pair(k0), pair(k0+8)}
            const uint2 ua = *(const uint2*)&s_arowh[kc + ko];
            const uint2 u0 = *(const uint2*)&s_bp[buf][r0     ][ko];
            const uint2 u1 = *(const uint2*)&s_bp[buf][r0 +  8][ko];
            const uint2 u2 = *(const uint2*)&s_bp[buf][r0 + 16][ko];
            const uint2 u3 = *(const uint2*)&s_bp[buf][r0 + 24][ko];
            uint32_t a0[4], a1[4];
            a0[0] = fragAB(ua.x, u0.x);
            a0[1] = fragAB(ua.x, u1.x);
            a0[2] = fragAB(ua.y, u0.y);
            a0[3] = fragAB(ua.y, u1.y);
            a1[0] = fragAB(ua.x, u2.x);
            a1[1] = fragAB(ua.x, u3.x);
            a1[2] = fragAB(ua.y, u2.y);
            a1[3] = fragAB(ua.y, u3.y);

            // ---- 32 MMAs on the current B slice ----
            #pragma unroll
            for (int p = 0; p < 8; p++) {
                mma_f16(acc[0][2 * p + 0], a0, cur[p].x, cur[p].y);
                mma_f16(acc[0][2 * p + 1], a0, cur[p].z, cur[p].w);
                mma_f16(acc[1][2 * p + 0], a1, cur[p].x, cur[p].y);
                mma_f16(acc[1][2 * p + 1], a1, cur[p].z, cur[p].w);
            }
        }
    }

    // ---- epilogue: out[row] = sum_j relu(D[row,j]+b2[j])*w3[j] + b3 ----
    float p0 = 0.0f, p1 = 0.0f, p2s = 0.0f, p3s = 0.0f;  // rows r0,+8,+16,+24
    #pragma unroll
    for (int nt = 0; nt < 16; nt++) {
        const int j = wc * 128 + nt * 8 + 2 * tg;
        const float b2a = s_b2[j], b2b = s_b2[j + 1];
        const float w3a = s_w3[j], w3b = s_w3[j + 1];
        const float* c0 = acc[0][nt];
        const float* c1 = acc[1][nt];
        p0  += fmaxf(c0[0] + b2a, 0.0f) * w3a + fmaxf(c0[1] + b2b, 0.0f) * w3b;
        p1  += fmaxf(c0[2] + b2a, 0.0f) * w3a + fmaxf(c0[3] + b2b, 0.0f) * w3b;
        p2s += fmaxf(c1[0] + b2a, 0.0f) * w3a + fmaxf(c1[1] + b2b, 0.0f) * w3b;
        p3s += fmaxf(c1[2] + b2a, 0.0f) * w3a + fmaxf(c1[3] + b2b, 0.0f) * w3b;
    }
    #pragma unroll
    for (int off = 1; off < 4; off <<= 1) {
        p0  += __shfl_xor_sync(0xffffffffu, p0, off);
        p1  += __shfl_xor_sync(0xffffffffu, p1, off);
        p2s += __shfl_xor_sync(0xffffffffu, p2s, off);
        p3s += __shfl_xor_sync(0xffffffffu, p3s, off);
    }

    __syncthreads();
    if (tg == 0) {
        s_part[(r0     ) * 2 + wc] = p0;
        s_part[(r0 +  8) * 2 + wc] = p1;
        s_part[(r0 + 16) * 2 + wc] = p2s;
        s_part[(r0 + 24) * 2 + wc] = p3s;
    }
    __syncthreads();
    if (tid < 64) {
        float v = s_part[tid * 2 + 0] + s_part[tid * 2 + 1] + b3[0];
        out[(size_t)(b * N_DIM + n) * M_DIM + m0 + tid] = v;
    }
}

// ============================================================================
// Launch
// ============================================================================
extern "C" void kernel_launch(void* const* d_in, const int* in_sizes, int n_in,
                              void* d_out, int out_size) {
    const float* PhiA = (const float*)d_in[0];
    const float* PhiB = (const float*)d_in[1];
    const float* W1a  = (const float*)d_in[2];
    const float* W1b  = (const float*)d_in[3];
    const float* b1   = (const float*)d_in[4];
    const float* W2   = (const float*)d_in[5];
    const float* b2   = (const float*)d_in[6];
    const float* W3   = (const float*)d_in[7];
    const float* b3   = (const float*)d_in[8];
    float* out = (float*)d_out;

    __half* aprojh = nullptr;
    __half* bprojh = nullptr;
    uint4 *w2f = nullptr, *w1af = nullptr, *w1bf = nullptr;
    cudaGetSymbolAddress((void**)&aprojh, g_aprojh);
    cudaGetSymbolAddress((void**)&bprojh, g_bprojh);
    cudaGetSymbolAddress((void**)&w2f, g_w2frag);
    cudaGetSymbolAddress((void**)&w1af, g_w1afrag);
    cudaGetSymbolAddress((void**)&w1bf, g_w1bfrag);

    // fragment all weight matrices (W2, W1a, W1b)
    wfrag_kernel<<<dim3(36, 32, 3), 32>>>(W2, W1a, W1b, w2f, w1af, w1bf);
    // tensor-core projections -> k-permuted fp16 aproj/bproj
    proj_mma_kernel<<<dim3((B_DIM * N_DIM + B_DIM * M_DIM) / 32, H1_DIM / 128), 128>>>(
        PhiA, PhiB, b1, w1af, w1bf, aprojh, bprojh);
    // fused pairwise MLP
    pair_mlp_main<<<B_DIM * N_DIM * (M_DIM / 64), 128>>>(
        aprojh, bprojh, w2f, b2, W3, b3, out);
}